// round 3
// baseline (speedup 1.0000x reference)
#include <cuda_runtime.h>
#include <cuda_bf16.h>
#include <mma.h>

using namespace nvcuda;

#define NN 8192
#define HH 64
#define LQ 72            // padded leading dim (elements) for all smem tiles

// Scratch (no allocation allowed)
__device__ float g_h[NN * HH];
__device__ float g_aggp[2][NN * HH];   // split-KV partial numerators
__device__ float g_denp[2][NN];        // split-KV partial denominators
__device__ __nv_bfloat16 g_qb[NN * HH];
__device__ __nv_bfloat16 g_kb[NN * HH];
__device__ __nv_bfloat16 g_mb[NN * HH];
__device__ float g_scal[2];   // [0] = gate_factor/8, [1] = stateful_bias[0]*(1-tc0)

// ---------------------------------------------------------------------------
// Fast exp on the FMA pipe. exp(-1e9) -> ~1.2e-38 (effectively 0, matches ref).
__device__ __forceinline__ float fexp(float x) {
    float t = x * 1.4426950408889634f;
    t = fmaxf(t, -126.0f);
    float r = rintf(t);
    float f = t - r;
    float p = fmaf(f, 0.0096181291f, 0.0555041087f);
    p = fmaf(f, p, 0.2402265070f);
    p = fmaf(f, p, 0.6931471806f);
    p = fmaf(f, p, 1.0f);
    return __int_as_float(((int)r + 127) << 23) * p;
}

// ---------------------------------------------------------------------------
__global__ void k_scalars(const float* __restrict__ tc, const float* __restrict__ wg,
                          const float* __restrict__ bg, const float* __restrict__ sb) {
    int t = threadIdx.x;  // 64 threads
    float v = fmaf(tc[0], wg[t], fmaf(tc[1], wg[64 + t], bg[t]));
    v = 1.0f / (1.0f + __expf(-v));
#pragma unroll
    for (int o = 16; o >= 1; o >>= 1) v += __shfl_xor_sync(0xffffffffu, v, o);
    __shared__ float red[2];
    if ((t & 31) == 0) red[t >> 5] = v;
    __syncthreads();
    if (t == 0) {
        float g = (red[0] + red[1]) * (1.0f / 64.0f);
        g_scal[0] = g * 0.125f;
        g_scal[1] = sb[0] * (1.0f - tc[0]);
    }
}

// ---------------------------------------------------------------------------
__device__ __forceinline__ void loadW(float* sW, const float* __restrict__ w, int tid) {
    float4* d = (float4*)sW;
    const float4* s = (const float4*)w;
#pragma unroll
    for (int k2 = 0; k2 < 4; k2++) d[tid + k2 * 256] = s[tid + k2 * 256];
}

__device__ __forceinline__ void gemm64(const float* __restrict__ sIn, const float* __restrict__ sW,
                                       const float* __restrict__ bias, int r0, int c0,
                                       float acc[4][4]) {
    float4 bb = *(const float4*)&bias[c0];
#pragma unroll
    for (int i = 0; i < 4; i++) {
        acc[i][0] = bb.x; acc[i][1] = bb.y; acc[i][2] = bb.z; acc[i][3] = bb.w;
    }
#pragma unroll 8
    for (int j = 0; j < 64; j++) {
        float4 wv = *(const float4*)&sW[j * 64 + c0];
#pragma unroll
        for (int i = 0; i < 4; i++) {
            float av = sIn[(r0 + i) * 64 + j];
            acc[i][0] = fmaf(av, wv.x, acc[i][0]);
            acc[i][1] = fmaf(av, wv.y, acc[i][1]);
            acc[i][2] = fmaf(av, wv.z, acc[i][2]);
            acc[i][3] = fmaf(av, wv.w, acc[i][3]);
        }
    }
}

__device__ __forceinline__ void store_bf16_row4(__nv_bfloat16* dst, const float* a, float s) {
    __nv_bfloat162 v01, v23;
    v01.x = __float2bfloat16(a[0] * s); v01.y = __float2bfloat16(a[1] * s);
    v23.x = __float2bfloat16(a[2] * s); v23.y = __float2bfloat16(a[3] * s);
    ((__nv_bfloat162*)dst)[0] = v01;
    ((__nv_bfloat162*)dst)[1] = v23;
}

__global__ __launch_bounds__(256) void k_prep(
    const float* __restrict__ nf, const float* __restrict__ tc,
    const float* __restrict__ w1, const float* __restrict__ b1,
    const float* __restrict__ w2, const float* __restrict__ b2,
    const float* __restrict__ wq, const float* __restrict__ bq,
    const float* __restrict__ wk, const float* __restrict__ bk,
    const float* __restrict__ wm, const float* __restrict__ bm) {
    __shared__ float sA[64 * 64];
    __shared__ float sW[64 * 64];
    const int tid = threadIdx.x;
    const int r0 = (tid >> 4) << 2;
    const int c0 = (tid & 15) << 2;
    const int q0 = blockIdx.x * 64;
    const float tc0 = tc[0], tc1 = tc[1];

    float x0[4], x1[4], x2[4];
#pragma unroll
    for (int i = 0; i < 4; i++) {
        int row = q0 + r0 + i;
        x0[i] = nf[row * 3 + 0]; x1[i] = nf[row * 3 + 1]; x2[i] = nf[row * 3 + 2];
    }
#pragma unroll
    for (int c = 0; c < 4; c++) {
        int col = c0 + c;
        float wv0 = w1[col], wv1 = w1[64 + col], wv2 = w1[128 + col];
        float bb = fmaf(tc0, w1[192 + col], fmaf(tc1, w1[256 + col], b1[col]));
#pragma unroll
        for (int i = 0; i < 4; i++) {
            float a = fmaf(x0[i], wv0, fmaf(x1[i], wv1, fmaf(x2[i], wv2, bb)));
            sA[(r0 + i) * 64 + col] = fmaxf(a, 0.0f);
        }
    }
    __syncthreads();

    loadW(sW, w2, tid);
    __syncthreads();
    float acc[4][4];
    gemm64(sA, sW, b2, r0, c0, acc);
    __syncthreads();
#pragma unroll
    for (int i = 0; i < 4; i++) {
        float4 hv = make_float4(acc[i][0], acc[i][1], acc[i][2], acc[i][3]);
        *(float4*)&sA[(r0 + i) * 64 + c0] = hv;
        *(float4*)&g_h[(q0 + r0 + i) * 64 + c0] = hv;
    }
    __syncthreads();

    loadW(sW, wq, tid);
    __syncthreads();
    gemm64(sA, sW, bq, r0, c0, acc);
    {
        float qs = g_scal[0];
#pragma unroll
        for (int i = 0; i < 4; i++)
            store_bf16_row4(&g_qb[(q0 + r0 + i) * 64 + c0], acc[i], qs);
    }
    __syncthreads();

    loadW(sW, wk, tid);
    __syncthreads();
    gemm64(sA, sW, bk, r0, c0, acc);
#pragma unroll
    for (int i = 0; i < 4; i++)
        store_bf16_row4(&g_kb[(q0 + r0 + i) * 64 + c0], acc[i], 1.0f);
    __syncthreads();

    loadW(sW, wm, tid);
    __syncthreads();
    gemm64(sA, sW, bm, r0, c0, acc);
#pragma unroll
    for (int i = 0; i < 4; i++)
        store_bf16_row4(&g_mb[(q0 + r0 + i) * 64 + c0], acc[i], 1.0f);
}

// ---------------------------------------------------------------------------
// K2: fused flash-attention, split-KV x2, padded smem (conflict-free ldmatrix),
// double-buffered K/V, 2 syncs/iter, 2 CTAs/SM.
#define SQ_OFF   0
#define SK_OFF   9216
#define SV_OFF   27648
#define SS_OFF   46080
#define SP_OFF   64512
#define STQ_OFF  73728
#define STK_OFF  73984
#define SMEM_ATTN 74496

__global__ __launch_bounds__(256, 2) void k_attn(const float* __restrict__ adj,
                                                 const float* __restrict__ nf) {
    extern __shared__ __align__(16) char dsm[];
    __nv_bfloat16* sQ = (__nv_bfloat16*)(dsm + SQ_OFF);
    __nv_bfloat16* sK = (__nv_bfloat16*)(dsm + SK_OFF);   // [2][64*LQ]
    __nv_bfloat16* sV = (__nv_bfloat16*)(dsm + SV_OFF);   // [2][64*LQ]
    float*         sS = (float*)(dsm + SS_OFF);           // [64*LQ]
    __nv_bfloat16* sP = (__nv_bfloat16*)(dsm + SP_OFF);   // [64*LQ]
    float*       sStQ = (float*)(dsm + STQ_OFF);
    float*       sStK = (float*)(dsm + STK_OFF);          // [2][64]

    const int tid = threadIdx.x;
    const int warp = tid >> 5;
    const int wm_ = warp >> 1;
    const int wn_ = warp & 1;
    const int rgrp = tid >> 4;
    const int fidx = tid & 15;
    const int qi = blockIdx.x >> 1;
    const int sp = blockIdx.x & 1;
    const int q0 = qi * 64;
    const int kvb = sp * 4096;
    const int d0 = (tid >> 3) * LQ + (tid & 7) * 8;  // staging dst for linear idx=tid
    const int BUF = 64 * LQ;

    // Stage Q (padded)
    {
        const uint4* qs = (const uint4*)(g_qb + q0 * 64);
        uint4 qa = qs[tid], qb = qs[tid + 256];
        *(uint4*)&sQ[d0] = qa;
        *(uint4*)&sQ[d0 + 32 * LQ] = qb;
    }
    if (tid < 64) sStQ[tid] = nf[(q0 + tid) * 3 + 2];
    const float sbc = g_scal[1];

    const uint4* ks = (const uint4*)(g_kb + kvb * 64);
    const uint4* vs = (const uint4*)(g_mb + kvb * 64);

    // Tile 0 -> buf 0
    {
        uint4 ka = ks[tid], kb2 = ks[tid + 256], va = vs[tid], vb = vs[tid + 256];
        *(uint4*)&sK[d0] = ka;            *(uint4*)&sK[d0 + 32 * LQ] = kb2;
        *(uint4*)&sV[d0] = va;            *(uint4*)&sV[d0 + 32 * LQ] = vb;
        if (tid < 64) sStK[tid] = nf[(kvb + tid) * 3 + 2];
    }
    // Prefetch tile 1 (regs)
    uint4 kr0 = ks[512 + tid], kr1 = ks[512 + tid + 256];
    uint4 vr0 = vs[512 + tid], vr1 = vs[512 + tid + 256];
    float stk = (tid < 64) ? nf[(kvb + 64 + tid) * 3 + 2] : 0.0f;
    // Prefetch adj tile 0 (regs)
    float4 a0, a1, a2, a3;
    {
        const float* ap = adj + (size_t)q0 * NN + kvb;
        a0 = *(const float4*)&ap[(size_t)(rgrp)      * NN + fidx * 4];
        a1 = *(const float4*)&ap[(size_t)(rgrp + 16) * NN + fidx * 4];
        a2 = *(const float4*)&ap[(size_t)(rgrp + 32) * NN + fidx * 4];
        a3 = *(const float4*)&ap[(size_t)(rgrp + 48) * NN + fidx * 4];
    }

    float den[4] = {0.f, 0.f, 0.f, 0.f};
    wmma::fragment<wmma::accumulator, 16, 16, 16, float> o0, o1;
    wmma::fill_fragment(o0, 0.0f);
    wmma::fill_fragment(o1, 0.0f);
    __syncthreads();

    for (int t = 0; t < 64; t++) {
        const int b = t & 1;
        const __nv_bfloat16* sKb = sK + b * BUF;
        const __nv_bfloat16* sVb = sV + b * BUF;

        // S = Q @ K^T
        {
            wmma::fragment<wmma::accumulator, 16, 16, 16, float> s0, s1;
            wmma::fill_fragment(s0, 0.0f);
            wmma::fill_fragment(s1, 0.0f);
#pragma unroll
            for (int kk = 0; kk < 4; kk++) {
                wmma::fragment<wmma::matrix_a, 16, 16, 16, __nv_bfloat16, wmma::row_major> fa;
                wmma::load_matrix_sync(fa, sQ + wm_ * 16 * LQ + kk * 16, LQ);
                wmma::fragment<wmma::matrix_b, 16, 16, 16, __nv_bfloat16, wmma::col_major> fb0, fb1;
                wmma::load_matrix_sync(fb0, sKb + (wn_ * 32)      * LQ + kk * 16, LQ);
                wmma::load_matrix_sync(fb1, sKb + (wn_ * 32 + 16) * LQ + kk * 16, LQ);
                wmma::mma_sync(s0, fa, fb0, s0);
                wmma::mma_sync(s1, fa, fb1, s1);
            }
            wmma::store_matrix_sync(sS + wm_ * 16 * LQ + wn_ * 32,      s0, LQ, wmma::mem_row_major);
            wmma::store_matrix_sync(sS + wm_ * 16 * LQ + wn_ * 32 + 16, s1, LQ, wmma::mem_row_major);
        }
        __syncthreads();   // (A)

        // Pointwise: P = exp(S + topo + sb); row-sums
        {
            float stqv[4] = {sStQ[rgrp], sStQ[rgrp + 16], sStQ[rgrp + 32], sStQ[rgrp + 48]};
            float stkv[4];
#pragma unroll
            for (int c = 0; c < 4; c++) stkv[c] = sStK[b * 64 + fidx * 4 + c];
            float4 av[4] = {a0, a1, a2, a3};
#pragma unroll
            for (int i = 0; i < 4; i++) {
                int row = rgrp + 16 * i;
                float4 sv = *(const float4*)&sS[row * LQ + fidx * 4];
                const float* ap2 = &av[i].x;
                const float* sp2 = &sv.x;
                float pv[4];
                float r = 0.0f;
#pragma unroll
                for (int c = 0; c < 4; c++) {
                    float a = ap2[c];
                    float topo = (a == 0.0f) ? -1e9f : a;
                    float s = sp2[c] + topo + sbc * stqv[i] * stkv[c];
                    float p = fexp(s);
                    pv[c] = p;
                    r += p;
                }
                __nv_bfloat162 v01, v23;
                v01.x = __float2bfloat16(pv[0]); v01.y = __float2bfloat16(pv[1]);
                v23.x = __float2bfloat16(pv[2]); v23.y = __float2bfloat16(pv[3]);
                __nv_bfloat162* pd = (__nv_bfloat162*)&sP[row * LQ + fidx * 4];
                pd[0] = v01; pd[1] = v23;
                r += __shfl_xor_sync(0xffffffffu, r, 1);
                r += __shfl_xor_sync(0xffffffffu, r, 2);
                r += __shfl_xor_sync(0xffffffffu, r, 4);
                r += __shfl_xor_sync(0xffffffffu, r, 8);
                den[i] += r;
            }
        }

        // Store next K/V tile (regs -> other buffer)
        if (t < 63) {
            __nv_bfloat16* kd = sK + (b ^ 1) * BUF;
            __nv_bfloat16* vd = sV + (b ^ 1) * BUF;
            *(uint4*)&kd[d0] = kr0;            *(uint4*)&kd[d0 + 32 * LQ] = kr1;
            *(uint4*)&vd[d0] = vr0;            *(uint4*)&vd[d0 + 32 * LQ] = vr1;
            if (tid < 64) sStK[(b ^ 1) * 64 + tid] = stk;
        }
        // Prefetch K/V tile t+2 (regs)
        if (t < 62) {
            int off = (t + 2) * 512;
            kr0 = ks[off + tid]; kr1 = ks[off + tid + 256];
            vr0 = vs[off + tid]; vr1 = vs[off + tid + 256];
            if (tid < 64) stk = nf[(kvb + (t + 2) * 64 + tid) * 3 + 2];
        }
        // Prefetch adj tile t+1 (regs)
        if (t < 63) {
            const float* ap = adj + (size_t)q0 * NN + kvb + (t + 1) * 64;
            a0 = *(const float4*)&ap[(size_t)(rgrp)      * NN + fidx * 4];
            a1 = *(const float4*)&ap[(size_t)(rgrp + 16) * NN + fidx * 4];
            a2 = *(const float4*)&ap[(size_t)(rgrp + 32) * NN + fidx * 4];
            a3 = *(const float4*)&ap[(size_t)(rgrp + 48) * NN + fidx * 4];
        }
        __syncthreads();   // (B)

        // O += P @ V
#pragma unroll
        for (int kk = 0; kk < 4; kk++) {
            wmma::fragment<wmma::matrix_a, 16, 16, 16, __nv_bfloat16, wmma::row_major> fp;
            wmma::load_matrix_sync(fp, sP + wm_ * 16 * LQ + kk * 16, LQ);
            wmma::fragment<wmma::matrix_b, 16, 16, 16, __nv_bfloat16, wmma::row_major> fv0, fv1;
            wmma::load_matrix_sync(fv0, sVb + kk * 16 * LQ + wn_ * 32, LQ);
            wmma::load_matrix_sync(fv1, sVb + kk * 16 * LQ + wn_ * 32 + 16, LQ);
            wmma::mma_sync(o0, fp, fv0, o0);
            wmma::mma_sync(o1, fp, fv1, o1);
        }
    }

    // Write partial den
    if (fidx == 0) {
#pragma unroll
        for (int i = 0; i < 4; i++) g_denp[sp][q0 + rgrp + 16 * i] = den[i];
    }
    // Write partial numerator
    wmma::store_matrix_sync(sS + wm_ * 16 * LQ + wn_ * 32,      o0, LQ, wmma::mem_row_major);
    wmma::store_matrix_sync(sS + wm_ * 16 * LQ + wn_ * 32 + 16, o1, LQ, wmma::mem_row_major);
    __syncthreads();
#pragma unroll
    for (int k2 = 0; k2 < 16; k2++) {
        int idx = tid + k2 * 256;
        int row = idx >> 6;
        int col = idx & 63;
        g_aggp[sp][(q0 + row) * 64 + col] = sS[row * LQ + col];
    }
}

// ---------------------------------------------------------------------------
// K3: combine partials; z = h + num/den ; LayerNorm ; head MLP. 4 rows/warp.
__global__ __launch_bounds__(256) void k_epi(
    const float* __restrict__ sa, const float* __restrict__ lng, const float* __restrict__ lnb,
    const float* __restrict__ wa1, const float* __restrict__ ba1,
    const float* __restrict__ wa2, const float* __restrict__ ba2,
    float* __restrict__ out) {
    __shared__ float sAi[32][68];
    const int warp = threadIdx.x >> 5;
    const int lane = threadIdx.x & 31;
    const int base = blockIdx.x * 32 + warp * 4;
    const int c0 = lane, c1 = lane + 32;

#pragma unroll
    for (int r = 0; r < 4; r++) {
        int row = base + r;
        float invd = 1.0f / (g_denp[0][row] + g_denp[1][row]);
        float z0 = g_h[row * 64 + c0] + (g_aggp[0][row * 64 + c0] + g_aggp[1][row * 64 + c0]) * invd;
        float z1 = g_h[row * 64 + c1] + (g_aggp[0][row * 64 + c1] + g_aggp[1][row * 64 + c1]) * invd;
        float s = z0 + z1;
#pragma unroll
        for (int o = 16; o >= 1; o >>= 1) s += __shfl_xor_sync(0xffffffffu, s, o);
        float mu = s * (1.0f / 64.0f);
        float d0 = z0 - mu, d1 = z1 - mu;
        float v = d0 * d0 + d1 * d1;
#pragma unroll
        for (int o = 16; o >= 1; o >>= 1) v += __shfl_xor_sync(0xffffffffu, v, o);
        float inv = rsqrtf(v * (1.0f / 64.0f) + 1e-5f);
        sAi[warp * 4 + r][c0] = fmaf(d0 * inv, lng[c0], lnb[c0]);
        sAi[warp * 4 + r][c1] = fmaf(d1 * inv, lng[c1], lnb[c1]);
        if (lane < 2) sAi[warp * 4 + r][64 + lane] = sa[row * 2 + lane];
    }
    __syncwarp();

    float acc0[4], acc1[4];
    float bb0 = ba1[c0], bb1 = ba1[c1];
#pragma unroll
    for (int r = 0; r < 4; r++) { acc0[r] = bb0; acc1[r] = bb1; }
#pragma unroll 6
    for (int i = 0; i < 66; i++) {
        float w0 = wa1[i * 64 + c0];
        float w1v = wa1[i * 64 + c1];
#pragma unroll
        for (int r = 0; r < 4; r++) {
            acc0[r] = fmaf(sAi[warp * 4 + r][i], w0, acc0[r]);
            acc1[r] = fmaf(sAi[warp * 4 + r][i], w1v, acc1[r]);
        }
    }
    float w20 = wa2[c0 * 3 + 0], w21 = wa2[c0 * 3 + 1], w22 = wa2[c0 * 3 + 2];
    float w30 = wa2[c1 * 3 + 0], w31 = wa2[c1 * 3 + 1], w32 = wa2[c1 * 3 + 2];
#pragma unroll
    for (int r = 0; r < 4; r++) {
        float p0 = fmaxf(acc0[r], 0.0f);
        float p1 = fmaxf(acc1[r], 0.0f);
        float q0v = fmaf(p0, w20, p1 * w30);
        float q1v = fmaf(p0, w21, p1 * w31);
        float q2v = fmaf(p0, w22, p1 * w32);
#pragma unroll
        for (int o = 16; o >= 1; o >>= 1) {
            q0v += __shfl_xor_sync(0xffffffffu, q0v, o);
            q1v += __shfl_xor_sync(0xffffffffu, q1v, o);
            q2v += __shfl_xor_sync(0xffffffffu, q2v, o);
        }
        if (lane == 0) {
            int row = base + r;
            out[row * 3 + 0] = q0v + ba2[0];
            out[row * 3 + 1] = q1v + ba2[1];
            out[row * 3 + 2] = q2v + ba2[2];
        }
    }
}

// ---------------------------------------------------------------------------
extern "C" void kernel_launch(void* const* d_in, const int* in_sizes, int n_in,
                              void* d_out, int out_size) {
    const float* nf    = (const float*)d_in[0];
    const float* adj   = (const float*)d_in[1];
    const float* tc    = (const float*)d_in[2];
    const float* sa    = (const float*)d_in[3];
    const float* w1    = (const float*)d_in[4];
    const float* b1    = (const float*)d_in[5];
    const float* w2    = (const float*)d_in[6];
    const float* b2    = (const float*)d_in[7];
    const float* wq    = (const float*)d_in[8];
    const float* bq    = (const float*)d_in[9];
    const float* wk    = (const float*)d_in[10];
    const float* bk    = (const float*)d_in[11];
    const float* wg    = (const float*)d_in[12];
    const float* bg    = (const float*)d_in[13];
    const float* sbias = (const float*)d_in[14];
    const float* wm    = (const float*)d_in[15];
    const float* bm    = (const float*)d_in[16];
    const float* lng   = (const float*)d_in[17];
    const float* lnb   = (const float*)d_in[18];
    const float* wa1   = (const float*)d_in[19];
    const float* ba1   = (const float*)d_in[20];
    const float* wa2   = (const float*)d_in[21];
    const float* ba2   = (const float*)d_in[22];
    float* out = (float*)d_out;

    static bool attr_set = false;
    if (!attr_set) {
        cudaFuncSetAttribute(k_attn, cudaFuncAttributeMaxDynamicSharedMemorySize, SMEM_ATTN);
        attr_set = true;
    }

    k_scalars<<<1, 64>>>(tc, wg, bg, sbias);
    k_prep<<<128, 256>>>(nf, tc, w1, b1, w2, b2, wq, bq, wk, bk, wm, bm);
    k_attn<<<256, 256, SMEM_ATTN>>>(adj, nf);
    k_epi<<<256, 256>>>(sa, lng, lnb, wa1, ba1, wa2, ba2, out);
}

// round 7
// speedup vs baseline: 1.7802x; 1.7802x over previous
#include <cuda_runtime.h>
#include <cuda.h>
#include <cuda_bf16.h>

#define NN 8192
#define L2E 1.4426950408889634f
#define SPLIT 8
#define TILES 16

// smem layout (bytes)
#define ADJ_OFF 0            // 2 x 32768
#define K_OFF   65536        // 2 x 8192
#define V_OFF   81920        // 2 x 8192
#define STK_OFF 98304        // 2 x 256
#define MB_OFF  98816        // 2 x 8
#define SMEM_SZ 98944

// Scratch (no allocation allowed)
__device__ float g_h[NN * 64];
__device__ float g_aggp[SPLIT][NN * 64];
__device__ float g_denp[SPLIT][NN];
__device__ __nv_bfloat16 g_qb[NN * 64];
__device__ __nv_bfloat16 g_kb[NN * 64];
__device__ __nv_bfloat16 g_mb[NN * 64];
__device__ float g_stk[NN];
__device__ float g_scal[2];  // [0]=gate/8*log2e  [1]=stateful_bias*(1-tc0)

// ---------------------------------------------------------------------------
__device__ __forceinline__ unsigned s2u(const void* p) {
    return (unsigned)__cvta_generic_to_shared(p);
}
__device__ __forceinline__ void cpa16(unsigned d, const void* s) {
    asm volatile("cp.async.cg.shared.global [%0],[%1],16;" :: "r"(d), "l"(s));
}
__device__ __forceinline__ void cpa4(unsigned d, const void* s) {
    asm volatile("cp.async.ca.shared.global [%0],[%1],4;" :: "r"(d), "l"(s));
}
__device__ __forceinline__ void cpcommit() { asm volatile("cp.async.commit_group;"); }
template <int N> __device__ __forceinline__ void cpwait() {
    asm volatile("cp.async.wait_group %0;" :: "n"(N));
}
__device__ __forceinline__ void mb_init(unsigned a, unsigned c) {
    asm volatile("mbarrier.init.shared.b64 [%0], %1;" :: "r"(a), "r"(c));
}
__device__ __forceinline__ void mb_exptx(unsigned a, unsigned b) {
    asm volatile("mbarrier.arrive.expect_tx.shared.b64 _, [%0], %1;" :: "r"(a), "r"(b) : "memory");
}
__device__ __forceinline__ void mb_wait(unsigned a, unsigned ph) {
    asm volatile(
        "{\n\t.reg .pred P;\n\t"
        "W%=:\n\t"
        "mbarrier.try_wait.parity.acquire.cta.shared::cta.b64 P, [%0], %1, 0x989680;\n\t"
        "@!P bra W%=;\n\t}"
        :: "r"(a), "r"(ph) : "memory");
}
__device__ __forceinline__ void tma2d(unsigned long long m, unsigned dst, int x, int y, unsigned mb) {
    asm volatile(
        "cp.async.bulk.tensor.2d.shared::cta.global.tile.mbarrier::complete_tx::bytes "
        "[%0], [%1, {%2, %3}], [%4];"
        :: "r"(dst), "l"(m), "r"(x), "r"(y), "r"(mb) : "memory");
}
__device__ __forceinline__ void ldm4(unsigned r[4], unsigned a) {
    asm volatile("ldmatrix.sync.aligned.m8n8.x4.shared.b16 {%0,%1,%2,%3}, [%4];"
                 : "=r"(r[0]), "=r"(r[1]), "=r"(r[2]), "=r"(r[3]) : "r"(a));
}
__device__ __forceinline__ void ldm4t(unsigned r[4], unsigned a) {
    asm volatile("ldmatrix.sync.aligned.m8n8.x4.trans.shared.b16 {%0,%1,%2,%3}, [%4];"
                 : "=r"(r[0]), "=r"(r[1]), "=r"(r[2]), "=r"(r[3]) : "r"(a));
}
__device__ __forceinline__ void mma16(float d[4], const unsigned a[4], unsigned b0, unsigned b1) {
    asm volatile("mma.sync.aligned.m16n8k16.row.col.f32.bf16.bf16.f32 "
                 "{%0,%1,%2,%3}, {%4,%5,%6,%7}, {%8,%9}, {%0,%1,%2,%3};"
                 : "+f"(d[0]), "+f"(d[1]), "+f"(d[2]), "+f"(d[3])
                 : "r"(a[0]), "r"(a[1]), "r"(a[2]), "r"(a[3]), "r"(b0), "r"(b1));
}

// P = adj * 2^t ; accumulates den. t is in log2 units, |t| small.
__device__ __forceinline__ float pexp(float t, float adj, float& den) {
    float rb = t + 12582912.0f;                    // 1.5*2^23 magic round
    int ib = __float_as_int(rb);
    float f = t - (rb - 12582912.0f);
    float p = fmaf(f, 0.0096181291f, 0.0555041087f);
    p = fmaf(f, p, 0.2402265070f);
    p = fmaf(f, p, 0.6931471806f);
    p = fmaf(f, p, 1.0f);
    float sc = __int_as_float((ib << 23) + 0x3f800000) * adj;
    float r = p * sc;
    den += r;
    return r;
}

// ---------------------------------------------------------------------------
__global__ void k_scalars(const float* __restrict__ tc, const float* __restrict__ wg,
                          const float* __restrict__ bg, const float* __restrict__ sb) {
    int t = threadIdx.x;  // 64 threads
    float v = fmaf(tc[0], wg[t], fmaf(tc[1], wg[64 + t], bg[t]));
    v = 1.0f / (1.0f + __expf(-v));
#pragma unroll
    for (int o = 16; o >= 1; o >>= 1) v += __shfl_xor_sync(0xffffffffu, v, o);
    __shared__ float red[2];
    if ((t & 31) == 0) red[t >> 5] = v;
    __syncthreads();
    if (t == 0) {
        float g = (red[0] + red[1]) * (1.0f / 64.0f);
        g_scal[0] = g * 0.125f * L2E;
        g_scal[1] = sb[0] * (1.0f - tc[0]);
    }
}

// ---------------------------------------------------------------------------
__device__ __forceinline__ void loadW(float* sW, const float* __restrict__ w, int tid) {
    float4* d = (float4*)sW;
    const float4* s = (const float4*)w;
#pragma unroll
    for (int k2 = 0; k2 < 4; k2++) d[tid + k2 * 256] = s[tid + k2 * 256];
}

__device__ __forceinline__ void gemm64(const float* __restrict__ sIn, const float* __restrict__ sW,
                                       const float* __restrict__ bias, int r0, int c0,
                                       float acc[4][4]) {
    float4 bb = *(const float4*)&bias[c0];
#pragma unroll
    for (int i = 0; i < 4; i++) {
        acc[i][0] = bb.x; acc[i][1] = bb.y; acc[i][2] = bb.z; acc[i][3] = bb.w;
    }
#pragma unroll 8
    for (int j = 0; j < 64; j++) {
        float4 wv = *(const float4*)&sW[j * 64 + c0];
#pragma unroll
        for (int i = 0; i < 4; i++) {
            float av = sIn[(r0 + i) * 64 + j];
            acc[i][0] = fmaf(av, wv.x, acc[i][0]);
            acc[i][1] = fmaf(av, wv.y, acc[i][1]);
            acc[i][2] = fmaf(av, wv.z, acc[i][2]);
            acc[i][3] = fmaf(av, wv.w, acc[i][3]);
        }
    }
}

__device__ __forceinline__ void store_bf16_row4(__nv_bfloat16* dst, const float* a, float s) {
    __nv_bfloat162 v01, v23;
    v01.x = __float2bfloat16(a[0] * s); v01.y = __float2bfloat16(a[1] * s);
    v23.x = __float2bfloat16(a[2] * s); v23.y = __float2bfloat16(a[3] * s);
    ((__nv_bfloat162*)dst)[0] = v01;
    ((__nv_bfloat162*)dst)[1] = v23;
}

__global__ __launch_bounds__(256) void k_prep(
    const float* __restrict__ nf, const float* __restrict__ tc,
    const float* __restrict__ w1, const float* __restrict__ b1,
    const float* __restrict__ w2, const float* __restrict__ b2,
    const float* __restrict__ wq, const float* __restrict__ bq,
    const float* __restrict__ wk, const float* __restrict__ bk,
    const float* __restrict__ wm, const float* __restrict__ bm) {
    __shared__ float sA[64 * 64];
    __shared__ float sW[64 * 64];
    const int tid = threadIdx.x;
    const int r0 = (tid >> 4) << 2;
    const int c0 = (tid & 15) << 2;
    const int q0 = blockIdx.x * 64;
    const float tc0 = tc[0], tc1 = tc[1];

    if (tid < 64) g_stk[q0 + tid] = nf[(q0 + tid) * 3 + 2];

    float x0[4], x1[4], x2[4];
#pragma unroll
    for (int i = 0; i < 4; i++) {
        int row = q0 + r0 + i;
        x0[i] = nf[row * 3 + 0]; x1[i] = nf[row * 3 + 1]; x2[i] = nf[row * 3 + 2];
    }
#pragma unroll
    for (int c = 0; c < 4; c++) {
        int col = c0 + c;
        float wv0 = w1[col], wv1 = w1[64 + col], wv2 = w1[128 + col];
        float bb = fmaf(tc0, w1[192 + col], fmaf(tc1, w1[256 + col], b1[col]));
#pragma unroll
        for (int i = 0; i < 4; i++) {
            float a = fmaf(x0[i], wv0, fmaf(x1[i], wv1, fmaf(x2[i], wv2, bb)));
            sA[(r0 + i) * 64 + col] = fmaxf(a, 0.0f);
        }
    }
    __syncthreads();

    loadW(sW, w2, tid);
    __syncthreads();
    float acc[4][4];
    gemm64(sA, sW, b2, r0, c0, acc);
    __syncthreads();
#pragma unroll
    for (int i = 0; i < 4; i++) {
        float4 hv = make_float4(acc[i][0], acc[i][1], acc[i][2], acc[i][3]);
        *(float4*)&sA[(r0 + i) * 64 + c0] = hv;
        *(float4*)&g_h[(q0 + r0 + i) * 64 + c0] = hv;
    }
    __syncthreads();

    loadW(sW, wq, tid);
    __syncthreads();
    gemm64(sA, sW, bq, r0, c0, acc);
    {
        float qs = g_scal[0];
#pragma unroll
        for (int i = 0; i < 4; i++)
            store_bf16_row4(&g_qb[(q0 + r0 + i) * 64 + c0], acc[i], qs);
    }
    __syncthreads();

    loadW(sW, wk, tid);
    __syncthreads();
    gemm64(sA, sW, bk, r0, c0, acc);
#pragma unroll
    for (int i = 0; i < 4; i++)
        store_bf16_row4(&g_kb[(q0 + r0 + i) * 64 + c0], acc[i], 1.0f);
    __syncthreads();

    loadW(sW, wm, tid);
    __syncthreads();
    gemm64(sA, sW, bm, r0, c0, acc);
#pragma unroll
    for (int i = 0; i < 4; i++)
        store_bf16_row4(&g_mb[(q0 + r0 + i) * 64 + c0], acc[i], 1.0f);
}

// ---------------------------------------------------------------------------
// K2: flash attention. BM=128 (8 warps x 16 rows), BN=64, split-KV x8.
// adj via TMA (SW128), K/V via cp.async (SW128), P register-resident.
__global__ __launch_bounds__(256) void k_attn(const __grid_constant__ CUtensorMap tmap) {
    extern __shared__ __align__(128) char dsm[];
    const unsigned su = s2u(dsm);
    const int tid = threadIdx.x;
    const int lane = tid & 31;
    const int wr = tid >> 5;
    const int r = lane >> 2;
    const int qd = lane & 3;
    const int c2 = qd << 1;
    const int qi = blockIdx.x >> 3;
    const int sp = blockIdx.x & 7;
    const int q0 = qi * 128;
    const int kvb = sp * 1024;
    const int gr = q0 + wr * 16 + r;
    const unsigned mbu = su + MB_OFF;

    if (tid == 0) { mb_init(mbu, 1); mb_init(mbu + 8, 1); }
    __syncthreads();

    const unsigned long long tmp = (unsigned long long)&tmap;
    if (tid == 0) {
        mb_exptx(mbu, 32768);
        tma2d(tmp, su + ADJ_OFF,         kvb,      q0, mbu);
        tma2d(tmp, su + ADJ_OFF + 16384, kvb + 32, q0, mbu);
        mb_exptx(mbu + 8, 32768);
        tma2d(tmp, su + ADJ_OFF + 32768, kvb + 64, q0, mbu + 8);
        tma2d(tmp, su + ADJ_OFF + 49152, kvb + 96, q0, mbu + 8);
    }

    // K/V staging (SW128 swizzled dense 64x64 bf16)
    const int srow = tid >> 3, sc = tid & 7;
    const unsigned sdof = (unsigned)(((srow << 7) + (sc << 4)) ^ (16 * (srow & 7)));
#define STAGE_KV(T, B)                                                              \
    {                                                                               \
        const __nv_bfloat16* kg = g_kb + (size_t)(kvb + (T) * 64) * 64;             \
        const __nv_bfloat16* vg = g_mb + (size_t)(kvb + (T) * 64) * 64;             \
        unsigned kd = su + K_OFF + (B) * 8192 + sdof;                               \
        unsigned vd = su + V_OFF + (B) * 8192 + sdof;                               \
        cpa16(kd, kg + srow * 64 + sc * 8);                                         \
        cpa16(kd + 4096, kg + (srow + 32) * 64 + sc * 8);                           \
        cpa16(vd, vg + srow * 64 + sc * 8);                                         \
        cpa16(vd + 4096, vg + (srow + 32) * 64 + sc * 8);                           \
        if (tid < 64) cpa4(su + STK_OFF + (B) * 256 + tid * 4, g_stk + kvb + (T) * 64 + tid); \
    }
    STAGE_KV(0, 0); cpcommit();
    STAGE_KV(1, 1); cpcommit();

    // Q fragments in registers (direct global loads)
    unsigned qf[4][4];
#pragma unroll
    for (int kk = 0; kk < 4; kk++) {
        const __nv_bfloat16* qp = g_qb + (size_t)gr * 64 + kk * 16 + c2;
        qf[kk][0] = *(const unsigned*)qp;
        qf[kk][1] = *(const unsigned*)(qp + 512);
        qf[kk][2] = *(const unsigned*)(qp + 8);
        qf[kk][3] = *(const unsigned*)(qp + 520);
    }
    const float sbl = g_scal[1] * L2E;
    const float crow0 = sbl * g_stk[gr];
    const float crow1 = sbl * g_stk[gr + 8];

    // lane-constant smem addressing
    const unsigned swz = 16u * (lane & 7);
    const unsigned lrowK = (((lane >> 4) & 1) << 3) + (lane & 7);
    const unsigned lrowV = (((lane >> 3) & 1) << 3) + (lane & 7);
    const unsigned kc16 = ((lane >> 3) & 1) << 4;
    const unsigned vc16 = ((lane >> 4) & 1) << 4;
    unsigned kcol[4], vcol[4];
#pragma unroll
    for (int i = 0; i < 4; i++) {
        kcol[i] = ((unsigned)(i << 5) + kc16) ^ swz;
        vcol[i] = ((unsigned)(i << 5) + vc16) ^ swz;
    }
    const unsigned arow128 = (unsigned)(wr * 16 + r) << 7;
    const unsigned acb = 8u * qd;
    const unsigned aswz = 16u * r;

    float Ot[8][4];
#pragma unroll
    for (int n = 0; n < 8; n++) { Ot[n][0] = Ot[n][1] = Ot[n][2] = Ot[n][3] = 0.f; }
    float den0 = 0.f, den1 = 0.f;

    for (int t = 0; t < TILES; t++) {
        const int b = t & 1;
        mb_wait(mbu + 8 * b, (t >> 1) & 1);
        cpwait<1>();
        __syncthreads();

        const unsigned kbase = su + K_OFF + b * 8192;
        const unsigned vbase = su + V_OFF + b * 8192;
        const char* adjb = dsm + b * 32768;
        const float* stkb = (const float*)(dsm + STK_OFF + b * 256);

        // S = Q @ K^T
        float S[8][4];
#pragma unroll
        for (int n = 0; n < 8; n++) { S[n][0] = S[n][1] = S[n][2] = S[n][3] = 0.f; }
#pragma unroll
        for (int jp = 0; jp < 4; jp++) {
            const unsigned rb = (unsigned)(16 * jp + lrowK) << 7;
#pragma unroll
            for (int kk = 0; kk < 4; kk++) {
                unsigned kf[4];
                ldm4(kf, kbase + rb + kcol[kk]);
                mma16(S[2 * jp],     qf[kk], kf[0], kf[1]);
                mma16(S[2 * jp + 1], qf[kk], kf[2], kf[3]);
            }
        }

        // pointwise: P = adj * 2^(S + crow*stk); den accumulate; pack to bf16x2
        unsigned pp[8][2];
#pragma unroll
        for (int n = 0; n < 8; n++) {
            float2 st = *(const float2*)(stkb + n * 8 + c2);
            unsigned ao = ((unsigned)(n >> 2) << 14) + arow128 +
                          ((acb + ((unsigned)(n & 3) << 5)) ^ aswz);
            float2 ad0 = *(const float2*)(adjb + ao);
            float2 ad1 = *(const float2*)(adjb + ao + 1024);
            float t00 = fmaf(crow0, st.x, S[n][0]);
            float t01 = fmaf(crow0, st.y, S[n][1]);
            float t10 = fmaf(crow1, st.x, S[n][2]);
            float t11 = fmaf(crow1, st.y, S[n][3]);
            float p00 = pexp(t00, ad0.x, den0);
            float p01 = pexp(t01, ad0.y, den0);
            float p10 = pexp(t10, ad1.x, den1);
            float p11 = pexp(t11, ad1.y, den1);
            asm("cvt.rn.bf16x2.f32 %0, %1, %2;" : "=r"(pp[n][0]) : "f"(p01), "f"(p00));
            asm("cvt.rn.bf16x2.f32 %0, %1, %2;" : "=r"(pp[n][1]) : "f"(p11), "f"(p10));
        }

        // O += P @ V   (P accumulator fragments reused directly as A operands)
#pragma unroll
        for (int dp = 0; dp < 4; dp++) {
#pragma unroll
            for (int kk = 0; kk < 4; kk++) {
                unsigned vf[4];
                ldm4t(vf, vbase + ((unsigned)(16 * kk + lrowV) << 7) + vcol[dp]);
                unsigned pa[4] = {pp[2 * kk][0], pp[2 * kk][1], pp[2 * kk + 1][0], pp[2 * kk + 1][1]};
                mma16(Ot[2 * dp],     pa, vf[0], vf[1]);
                mma16(Ot[2 * dp + 1], pa, vf[2], vf[3]);
            }
        }
        __syncthreads();

        if (t + 2 < TILES) {
            if (tid == 0) {
                mb_exptx(mbu + 8 * b, 32768);
                int x = kvb + (t + 2) * 64;
                tma2d(tmp, su + ADJ_OFF + b * 32768,         x,      q0, mbu + 8 * b);
                tma2d(tmp, su + ADJ_OFF + b * 32768 + 16384, x + 32, q0, mbu + 8 * b);
            }
            STAGE_KV(t + 2, b);
        }
        cpcommit();
    }

    // reduce den across quad, write partials
    den0 += __shfl_xor_sync(0xffffffffu, den0, 1);
    den0 += __shfl_xor_sync(0xffffffffu, den0, 2);
    den1 += __shfl_xor_sync(0xffffffffu, den1, 1);
    den1 += __shfl_xor_sync(0xffffffffu, den1, 2);
    if (qd == 0) {
        g_denp[sp][gr] = den0;
        g_denp[sp][gr + 8] = den1;
    }
#pragma unroll
    for (int n = 0; n < 8; n++) {
        float* o0 = &g_aggp[sp][(size_t)gr * 64 + n * 8 + c2];
        *(float2*)o0 = make_float2(Ot[n][0], Ot[n][1]);
        *(float2*)(o0 + 512) = make_float2(Ot[n][2], Ot[n][3]);
    }
}

// ---------------------------------------------------------------------------
// K3: combine 8 partials; z = h + num/den ; LayerNorm ; head MLP. warp-per-row.
__global__ __launch_bounds__(256) void k_epi(
    const float* __restrict__ sa, const float* __restrict__ lng, const float* __restrict__ lnb,
    const float* __restrict__ wa1, const float* __restrict__ ba1,
    const float* __restrict__ wa2, const float* __restrict__ ba2,
    float* __restrict__ out) {
    __shared__ float sAi[8][68];
    const int warp = threadIdx.x >> 5;
    const int lane = threadIdx.x & 31;
    const int row = blockIdx.x * 8 + warp;
    const int c0 = lane, c1 = lane + 32;

    float den = 0.f, n0 = 0.f, n1 = 0.f;
#pragma unroll
    for (int s = 0; s < SPLIT; s++) {
        den += g_denp[s][row];
        n0 += g_aggp[s][row * 64 + c0];
        n1 += g_aggp[s][row * 64 + c1];
    }
    float invd = 1.0f / den;
    float z0 = g_h[row * 64 + c0] + n0 * invd;
    float z1 = g_h[row * 64 + c1] + n1 * invd;
    float s = z0 + z1;
#pragma unroll
    for (int o = 16; o >= 1; o >>= 1) s += __shfl_xor_sync(0xffffffffu, s, o);
    float mu = s * (1.0f / 64.0f);
    float d0 = z0 - mu, d1 = z1 - mu;
    float v = d0 * d0 + d1 * d1;
#pragma unroll
    for (int o = 16; o >= 1; o >>= 1) v += __shfl_xor_sync(0xffffffffu, v, o);
    float inv = rsqrtf(v * (1.0f / 64.0f) + 1e-5f);
    sAi[warp][c0] = fmaf(d0 * inv, lng[c0], lnb[c0]);
    sAi[warp][c1] = fmaf(d1 * inv, lng[c1], lnb[c1]);
    if (lane < 2) sAi[warp][64 + lane] = sa[row * 2 + lane];
    __syncwarp();

    float acc0 = ba1[c0], acc1 = ba1[c1];
#pragma unroll 11
    for (int i = 0; i < 66; i++) {
        float av = sAi[warp][i];
        acc0 = fmaf(av, wa1[i * 64 + c0], acc0);
        acc1 = fmaf(av, wa1[i * 64 + c1], acc1);
    }
    acc0 = fmaxf(acc0, 0.0f);
    acc1 = fmaxf(acc1, 0.0f);
    float q0v = fmaf(acc0, wa2[c0 * 3 + 0], acc1 * wa2[c1 * 3 + 0]);
    float q1v = fmaf(acc0, wa2[c0 * 3 + 1], acc1 * wa2[c1 * 3 + 1]);
    float q2v = fmaf(acc0, wa2[c0 * 3 + 2], acc1 * wa2[c1 * 3 + 2]);
#pragma unroll
    for (int o = 16; o >= 1; o >>= 1) {
        q0v += __shfl_xor_sync(0xffffffffu, q0v, o);
        q1v += __shfl_xor_sync(0xffffffffu, q1v, o);
        q2v += __shfl_xor_sync(0xffffffffu, q2v, o);
    }
    if (lane == 0) {
        out[row * 3 + 0] = q0v + ba2[0];
        out[row * 3 + 1] = q1v + ba2[1];
        out[row * 3 + 2] = q2v + ba2[2];
    }
}

// ---------------------------------------------------------------------------
typedef CUresult (*PFN_tmEnc)(CUtensorMap*, CUtensorMapDataType, cuuint32_t, void*,
                              const cuuint64_t*, const cuuint64_t*, const cuuint32_t*,
                              const cuuint32_t*, CUtensorMapInterleave, CUtensorMapSwizzle,
                              CUtensorMapL2promotion, CUtensorMapFloatOOBfill);

extern "C" void kernel_launch(void* const* d_in, const int* in_sizes, int n_in,
                              void* d_out, int out_size) {
    const float* nf    = (const float*)d_in[0];
    const float* adj   = (const float*)d_in[1];
    const float* tc    = (const float*)d_in[2];
    const float* sa    = (const float*)d_in[3];
    const float* w1    = (const float*)d_in[4];
    const float* b1    = (const float*)d_in[5];
    const float* w2    = (const float*)d_in[6];
    const float* b2    = (const float*)d_in[7];
    const float* wq    = (const float*)d_in[8];
    const float* bq    = (const float*)d_in[9];
    const float* wk    = (const float*)d_in[10];
    const float* bk    = (const float*)d_in[11];
    const float* wg    = (const float*)d_in[12];
    const float* bg    = (const float*)d_in[13];
    const float* sbias = (const float*)d_in[14];
    const float* wm    = (const float*)d_in[15];
    const float* bm    = (const float*)d_in[16];
    const float* lng   = (const float*)d_in[17];
    const float* lnb   = (const float*)d_in[18];
    const float* wa1   = (const float*)d_in[19];
    const float* ba1   = (const float*)d_in[20];
    const float* wa2   = (const float*)d_in[21];
    const float* ba2   = (const float*)d_in[22];
    float* out = (float*)d_out;

    // adj tensormap: fp32 [8192, 8192], box [32, 128], SW128
    CUtensorMap tmap;
    {
        PFN_tmEnc fn = nullptr;
        cudaDriverEntryPointQueryResult st;
        cudaGetDriverEntryPoint("cuTensorMapEncodeTiled", (void**)&fn,
                                cudaEnableDefault, &st);
        cuuint64_t dims[2] = {NN, NN};
        cuuint64_t strides[1] = {NN * 4ull};
        cuuint32_t box[2] = {32, 128};
        cuuint32_t es[2] = {1, 1};
        fn(&tmap, CU_TENSOR_MAP_DATA_TYPE_FLOAT32, 2, (void*)adj, dims, strides, box, es,
           CU_TENSOR_MAP_INTERLEAVE_NONE, CU_TENSOR_MAP_SWIZZLE_128B,
           CU_TENSOR_MAP_L2_PROMOTION_L2_128B, CU_TENSOR_MAP_FLOAT_OOB_FILL_NONE);
    }
    cudaFuncSetAttribute(k_attn, cudaFuncAttributeMaxDynamicSharedMemorySize, SMEM_SZ);

    k_scalars<<<1, 64>>>(tc, wg, bg, sbias);
    k_prep<<<128, 256>>>(nf, tc, w1, b1, w2, b2, wq, bq, wk, bk, wm, bm);
    k_attn<<<512, 256, SMEM_SZ>>>(tmap);
    k_epi<<<1024, 256>>>(sa, lng, lnb, wa1, ba1, wa2, ba2, out);
}

// round 9
// speedup vs baseline: 1.9136x; 1.0749x over previous
#include <cuda_runtime.h>
#include <cuda.h>
#include <cuda_bf16.h>

#define NN 8192
#define L2E 1.4426950408889634f
#define SPLIT 8
#define TILES 16

// smem layout (bytes) for k_attn
#define ADJ_OFF 0            // 2 x 32768
#define K_OFF   65536        // 2 x 8192
#define V_OFF   81920        // 2 x 8192
#define STK_OFF 98304        // 2 x 256
#define MB_OFF  98816        // 2 x 8
#define SMEM_SZ 98944

// Scratch (no allocation allowed)
__device__ float g_h[NN * 64];
__device__ float g_aggp[SPLIT][NN * 64];
__device__ float g_denp[SPLIT][NN];
__device__ __nv_bfloat16 g_qb[NN * 64];
__device__ __nv_bfloat16 g_kb[NN * 64];
__device__ __nv_bfloat16 g_mb[NN * 64];
__device__ float g_stk[NN];

// ---------------------------------------------------------------------------
__device__ __forceinline__ unsigned s2u(const void* p) {
    return (unsigned)__cvta_generic_to_shared(p);
}
__device__ __forceinline__ void cpa16(unsigned d, const void* s) {
    asm volatile("cp.async.cg.shared.global [%0],[%1],16;" :: "r"(d), "l"(s));
}
__device__ __forceinline__ void cpa4(unsigned d, const void* s) {
    asm volatile("cp.async.ca.shared.global [%0],[%1],4;" :: "r"(d), "l"(s));
}
__device__ __forceinline__ void cpcommit() { asm volatile("cp.async.commit_group;"); }
template <int N> __device__ __forceinline__ void cpwait() {
    asm volatile("cp.async.wait_group %0;" :: "n"(N));
}
__device__ __forceinline__ void mb_init(unsigned a, unsigned c) {
    asm volatile("mbarrier.init.shared.b64 [%0], %1;" :: "r"(a), "r"(c));
}
__device__ __forceinline__ void mb_exptx(unsigned a, unsigned b) {
    asm volatile("mbarrier.arrive.expect_tx.shared.b64 _, [%0], %1;" :: "r"(a), "r"(b) : "memory");
}
__device__ __forceinline__ void mb_wait(unsigned a, unsigned ph) {
    asm volatile(
        "{\n\t.reg .pred P;\n\t"
        "W%=:\n\t"
        "mbarrier.try_wait.parity.acquire.cta.shared::cta.b64 P, [%0], %1, 0x989680;\n\t"
        "@!P bra W%=;\n\t}"
        :: "r"(a), "r"(ph) : "memory");
}
__device__ __forceinline__ void tma2d(unsigned long long m, unsigned dst, int x, int y, unsigned mb) {
    asm volatile(
        "cp.async.bulk.tensor.2d.shared::cta.global.tile.mbarrier::complete_tx::bytes "
        "[%0], [%1, {%2, %3}], [%4];"
        :: "r"(dst), "l"(m), "r"(x), "r"(y), "r"(mb) : "memory");
}
__device__ __forceinline__ void ldm4(unsigned r[4], unsigned a) {
    asm volatile("ldmatrix.sync.aligned.m8n8.x4.shared.b16 {%0,%1,%2,%3}, [%4];"
                 : "=r"(r[0]), "=r"(r[1]), "=r"(r[2]), "=r"(r[3]) : "r"(a));
}
__device__ __forceinline__ void ldm4t(unsigned r[4], unsigned a) {
    asm volatile("ldmatrix.sync.aligned.m8n8.x4.trans.shared.b16 {%0,%1,%2,%3}, [%4];"
                 : "=r"(r[0]), "=r"(r[1]), "=r"(r[2]), "=r"(r[3]) : "r"(a));
}
__device__ __forceinline__ void mma16(float d[4], const unsigned a[4], unsigned b0, unsigned b1) {
    asm volatile("mma.sync.aligned.m16n8k16.row.col.f32.bf16.bf16.f32 "
                 "{%0,%1,%2,%3}, {%4,%5,%6,%7}, {%8,%9}, {%0,%1,%2,%3};"
                 : "+f"(d[0]), "+f"(d[1]), "+f"(d[2]), "+f"(d[3])
                 : "r"(a[0]), "r"(a[1]), "r"(a[2]), "r"(a[3]), "r"(b0), "r"(b1));
}
__device__ __forceinline__ unsigned long long pk2(float x) {
    unsigned long long r;
    asm("mov.b64 %0, {%1, %1};" : "=l"(r) : "f"(x));
    return r;
}

// Packed pair: P = adj * 2^(S + crow*st) for two adjacent columns; accumulates
// packed den; returns bf16x2 (elem0 in low half). All f32x2 on the FMA pipe.
__device__ __forceinline__ unsigned pexp2(
    float s0, float s1, float stx, float sty, float crow, float a0, float a1,
    unsigned long long MAG2, unsigned long long NMAG2, unsigned long long NEG12,
    unsigned long long C4, unsigned long long C3, unsigned long long C2,
    unsigned long long C1, unsigned long long ONE2,
    unsigned long long& den2) {
    unsigned out;
    asm volatile(
        "{\n\t"
        ".reg .b64 S2, st2, cr2, ad2, t2, rb2, r2, f2, p2, sc2;\n\t"
        ".reg .b32 il, ih;\n\t"
        ".reg .f32 sl, sh, pl, ph;\n\t"
        "mov.b64 S2, {%2, %3};\n\t"
        "mov.b64 st2, {%4, %5};\n\t"
        "mov.b64 cr2, {%6, %6};\n\t"
        "mov.b64 ad2, {%7, %8};\n\t"
        "fma.rn.f32x2 t2, cr2, st2, S2;\n\t"
        "add.rn.f32x2 rb2, t2, %9;\n\t"
        "add.rn.f32x2 r2, rb2, %10;\n\t"
        "fma.rn.f32x2 f2, r2, %11, t2;\n\t"
        "fma.rn.f32x2 p2, f2, %12, %13;\n\t"
        "fma.rn.f32x2 p2, f2, p2, %14;\n\t"
        "fma.rn.f32x2 p2, f2, p2, %15;\n\t"
        "fma.rn.f32x2 p2, f2, p2, %16;\n\t"
        "mov.b64 {il, ih}, rb2;\n\t"
        "shl.b32 il, il, 23;\n\t"
        "shl.b32 ih, ih, 23;\n\t"
        "add.s32 il, il, 0x3f800000;\n\t"
        "add.s32 ih, ih, 0x3f800000;\n\t"
        "mov.b32 sl, il;\n\t"
        "mov.b32 sh, ih;\n\t"
        "mov.b64 sc2, {sl, sh};\n\t"
        "mul.rn.f32x2 sc2, sc2, ad2;\n\t"
        "mul.rn.f32x2 p2, p2, sc2;\n\t"
        "add.rn.f32x2 %1, %1, p2;\n\t"
        "mov.b64 {pl, ph}, p2;\n\t"
        "cvt.rn.bf16x2.f32 %0, ph, pl;\n\t"
        "}"
        : "=r"(out), "+l"(den2)
        : "f"(s0), "f"(s1), "f"(stx), "f"(sty), "f"(crow), "f"(a0), "f"(a1),
          "l"(MAG2), "l"(NMAG2), "l"(NEG12), "l"(C4), "l"(C3), "l"(C2),
          "l"(C1), "l"(ONE2));
    return out;
}

// ---------------------------------------------------------------------------
// K1: BM=32, grid 256 (2 CTAs/SM). Gate computed inline; k_scalars removed.
__device__ __forceinline__ void loadW(float* sW, const float* __restrict__ w, int tid) {
    float4* d = (float4*)sW;
    const float4* s = (const float4*)w;
#pragma unroll
    for (int k2 = 0; k2 < 4; k2++) d[tid + k2 * 256] = s[tid + k2 * 256];
}

__device__ __forceinline__ void gemm32(const float* __restrict__ sIn, const float* __restrict__ sW,
                                       const float* __restrict__ bias, int r0, int c0,
                                       float acc[2][4]) {
    float4 bb = *(const float4*)&bias[c0];
#pragma unroll
    for (int i = 0; i < 2; i++) {
        acc[i][0] = bb.x; acc[i][1] = bb.y; acc[i][2] = bb.z; acc[i][3] = bb.w;
    }
#pragma unroll 8
    for (int j = 0; j < 64; j++) {
        float4 wv = *(const float4*)&sW[j * 64 + c0];
#pragma unroll
        for (int i = 0; i < 2; i++) {
            float av = sIn[(r0 + i) * 64 + j];
            acc[i][0] = fmaf(av, wv.x, acc[i][0]);
            acc[i][1] = fmaf(av, wv.y, acc[i][1]);
            acc[i][2] = fmaf(av, wv.z, acc[i][2]);
            acc[i][3] = fmaf(av, wv.w, acc[i][3]);
        }
    }
}

__device__ __forceinline__ void store_bf16_row4(__nv_bfloat16* dst, const float* a, float s) {
    __nv_bfloat162 v01, v23;
    v01.x = __float2bfloat16(a[0] * s); v01.y = __float2bfloat16(a[1] * s);
    v23.x = __float2bfloat16(a[2] * s); v23.y = __float2bfloat16(a[3] * s);
    ((__nv_bfloat162*)dst)[0] = v01;
    ((__nv_bfloat162*)dst)[1] = v23;
}

__global__ __launch_bounds__(256) void k_prep(
    const float* __restrict__ nf, const float* __restrict__ tc,
    const float* __restrict__ w1, const float* __restrict__ b1,
    const float* __restrict__ w2, const float* __restrict__ b2,
    const float* __restrict__ wq, const float* __restrict__ bq,
    const float* __restrict__ wk, const float* __restrict__ bk,
    const float* __restrict__ wm, const float* __restrict__ bm,
    const float* __restrict__ wg, const float* __restrict__ bg) {
    __shared__ float sA[32 * 64];
    __shared__ float sW[64 * 64];
    __shared__ float sG[65];
    const int tid = threadIdx.x;
    const int r0 = (tid >> 4) << 1;
    const int c0 = (tid & 15) << 2;
    const int q0 = blockIdx.x * 32;
    const float tc0 = tc[0], tc1 = tc[1];

    if (tid < 32) g_stk[q0 + tid] = nf[(q0 + tid) * 3 + 2];
    if (tid < 64) {
        float v = fmaf(tc0, wg[tid], fmaf(tc1, wg[64 + tid], bg[tid]));
        sG[tid] = 1.0f / (1.0f + __expf(-v));
    }

    // Stage 0: a = relu(x @ w1 + b1)
    float x0[2], x1[2], x2[2];
#pragma unroll
    for (int i = 0; i < 2; i++) {
        int row = q0 + r0 + i;
        x0[i] = nf[row * 3 + 0]; x1[i] = nf[row * 3 + 1]; x2[i] = nf[row * 3 + 2];
    }
#pragma unroll
    for (int c = 0; c < 4; c++) {
        int col = c0 + c;
        float wv0 = w1[col], wv1 = w1[64 + col], wv2 = w1[128 + col];
        float bb = fmaf(tc0, w1[192 + col], fmaf(tc1, w1[256 + col], b1[col]));
#pragma unroll
        for (int i = 0; i < 2; i++) {
            float a = fmaf(x0[i], wv0, fmaf(x1[i], wv1, fmaf(x2[i], wv2, bb)));
            sA[(r0 + i) * 64 + col] = fmaxf(a, 0.0f);
        }
    }
    __syncthreads();
    if (tid == 0) {
        float s = 0.0f;
#pragma unroll 8
        for (int i = 0; i < 64; i++) s += sG[i];
        sG[64] = s * (1.0f / 64.0f) * 0.125f * L2E;   // gate/8 * log2e
    }

    loadW(sW, w2, tid);
    __syncthreads();
    float acc[2][4];
    gemm32(sA, sW, b2, r0, c0, acc);
    __syncthreads();
#pragma unroll
    for (int i = 0; i < 2; i++) {
        float4 hv = make_float4(acc[i][0], acc[i][1], acc[i][2], acc[i][3]);
        *(float4*)&sA[(r0 + i) * 64 + c0] = hv;
        *(float4*)&g_h[(q0 + r0 + i) * 64 + c0] = hv;
    }
    __syncthreads();

    loadW(sW, wq, tid);
    __syncthreads();
    gemm32(sA, sW, bq, r0, c0, acc);
    {
        float qs = sG[64];
#pragma unroll
        for (int i = 0; i < 2; i++)
            store_bf16_row4(&g_qb[(q0 + r0 + i) * 64 + c0], acc[i], qs);
    }
    __syncthreads();

    loadW(sW, wk, tid);
    __syncthreads();
    gemm32(sA, sW, bk, r0, c0, acc);
#pragma unroll
    for (int i = 0; i < 2; i++)
        store_bf16_row4(&g_kb[(q0 + r0 + i) * 64 + c0], acc[i], 1.0f);
    __syncthreads();

    loadW(sW, wm, tid);
    __syncthreads();
    gemm32(sA, sW, bm, r0, c0, acc);
#pragma unroll
    for (int i = 0; i < 2; i++)
        store_bf16_row4(&g_mb[(q0 + r0 + i) * 64 + c0], acc[i], 1.0f);
}

// ---------------------------------------------------------------------------
// K2: flash attention. BM=128, BN=64, split-KV x8. adj via TMA, packed-f32x2
// pointwise, register-resident P.
__global__ __launch_bounds__(256) void k_attn(const __grid_constant__ CUtensorMap tmap,
                                              const float* __restrict__ tc,
                                              const float* __restrict__ sb) {
    extern __shared__ __align__(128) char dsm[];
    const unsigned su = s2u(dsm);
    const int tid = threadIdx.x;
    const int lane = tid & 31;
    const int wr = tid >> 5;
    const int r = lane >> 2;
    const int qd = lane & 3;
    const int c2 = qd << 1;
    const int qi = blockIdx.x >> 3;
    const int sp = blockIdx.x & 7;
    const int q0 = qi * 128;
    const int kvb = sp * 1024;
    const int gr = q0 + wr * 16 + r;
    const unsigned mbu = su + MB_OFF;

    if (tid == 0) { mb_init(mbu, 1); mb_init(mbu + 8, 1); }
    __syncthreads();

    const unsigned long long tmp = (unsigned long long)&tmap;
    if (tid == 0) {
        mb_exptx(mbu, 32768);
        tma2d(tmp, su + ADJ_OFF,         kvb,      q0, mbu);
        tma2d(tmp, su + ADJ_OFF + 16384, kvb + 32, q0, mbu);
        mb_exptx(mbu + 8, 32768);
        tma2d(tmp, su + ADJ_OFF + 32768, kvb + 64, q0, mbu + 8);
        tma2d(tmp, su + ADJ_OFF + 49152, kvb + 96, q0, mbu + 8);
    }

    // K/V staging (SW128 swizzled dense 64x64 bf16)
    const int srow = tid >> 3, sc = tid & 7;
    const unsigned sdof = (unsigned)(((srow << 7) + (sc << 4)) ^ (16 * (srow & 7)));
#define STAGE_KV(T, B)                                                              \
    {                                                                               \
        const __nv_bfloat16* kg = g_kb + (size_t)(kvb + (T) * 64) * 64;             \
        const __nv_bfloat16* vg = g_mb + (size_t)(kvb + (T) * 64) * 64;             \
        unsigned kd = su + K_OFF + (B) * 8192 + sdof;                               \
        unsigned vd = su + V_OFF + (B) * 8192 + sdof;                               \
        cpa16(kd, kg + srow * 64 + sc * 8);                                         \
        cpa16(kd + 4096, kg + (srow + 32) * 64 + sc * 8);                           \
        cpa16(vd, vg + srow * 64 + sc * 8);                                         \
        cpa16(vd + 4096, vg + (srow + 32) * 64 + sc * 8);                           \
        if (tid < 64) cpa4(su + STK_OFF + (B) * 256 + tid * 4, g_stk + kvb + (T) * 64 + tid); \
    }
    STAGE_KV(0, 0); cpcommit();
    STAGE_KV(1, 1); cpcommit();

    // Q fragments in registers
    unsigned qf[4][4];
#pragma unroll
    for (int kk = 0; kk < 4; kk++) {
        const __nv_bfloat16* qp = g_qb + (size_t)gr * 64 + kk * 16 + c2;
        qf[kk][0] = *(const unsigned*)qp;
        qf[kk][1] = *(const unsigned*)(qp + 512);
        qf[kk][2] = *(const unsigned*)(qp + 8);
        qf[kk][3] = *(const unsigned*)(qp + 520);
    }
    const float sbl = sb[0] * (1.0f - tc[0]) * L2E;
    const float crow0 = sbl * g_stk[gr];
    const float crow1 = sbl * g_stk[gr + 8];

    // packed constants (warp-uniform -> UR promotion)
    const unsigned long long MAG2 = pk2(12582912.0f);
    const unsigned long long NMAG2 = pk2(-12582912.0f);
    const unsigned long long NEG12 = pk2(-1.0f);
    const unsigned long long C4 = pk2(0.0096181291f);
    const unsigned long long C3 = pk2(0.0555041087f);
    const unsigned long long C2 = pk2(0.2402265070f);
    const unsigned long long C1 = pk2(0.6931471806f);
    const unsigned long long ONE2 = pk2(1.0f);

    // lane-constant smem addressing
    const unsigned swz = 16u * (lane & 7);
    const unsigned lrowK = (((lane >> 4) & 1) << 3) + (lane & 7);
    const unsigned lrowV = (((lane >> 3) & 1) << 3) + (lane & 7);
    const unsigned kc16 = ((lane >> 3) & 1) << 4;
    const unsigned vc16 = ((lane >> 4) & 1) << 4;
    unsigned kcol[4], vcol[4];
#pragma unroll
    for (int i = 0; i < 4; i++) {
        kcol[i] = ((unsigned)(i << 5) + kc16) ^ swz;
        vcol[i] = ((unsigned)(i << 5) + vc16) ^ swz;
    }
    const unsigned arow128 = (unsigned)(wr * 16 + r) << 7;
    const unsigned acb = 8u * qd;
    const unsigned aswz = 16u * r;

    float Ot[8][4];
#pragma unroll
    for (int n = 0; n < 8; n++) { Ot[n][0] = Ot[n][1] = Ot[n][2] = Ot[n][3] = 0.f; }
    unsigned long long den0_2 = 0ull, den1_2 = 0ull;

    for (int t = 0; t < TILES; t++) {
        const int b = t & 1;
        mb_wait(mbu + 8 * b, (t >> 1) & 1);
        cpwait<1>();
        __syncthreads();

        const unsigned kbase = su + K_OFF + b * 8192;
        const unsigned vbase = su + V_OFF + b * 8192;
        const char* adjb = dsm + b * 32768;
        const float* stkb = (const float*)(dsm + STK_OFF + b * 256);

        // S = Q @ K^T
        float S[8][4];
#pragma unroll
        for (int n = 0; n < 8; n++) { S[n][0] = S[n][1] = S[n][2] = S[n][3] = 0.f; }
#pragma unroll
        for (int jp = 0; jp < 4; jp++) {
            const unsigned rb = (unsigned)(16 * jp + lrowK) << 7;
#pragma unroll
            for (int kk = 0; kk < 4; kk++) {
                unsigned kf[4];
                ldm4(kf, kbase + rb + kcol[kk]);
                mma16(S[2 * jp],     qf[kk], kf[0], kf[1]);
                mma16(S[2 * jp + 1], qf[kk], kf[2], kf[3]);
            }
        }

        // pointwise, packed pairs
        unsigned pp[8][2];
#pragma unroll
        for (int n = 0; n < 8; n++) {
            float2 st = *(const float2*)(stkb + n * 8 + c2);
            unsigned ao = ((unsigned)(n >> 2) << 14) + arow128 +
                          ((acb + ((unsigned)(n & 3) << 5)) ^ aswz);
            float2 ad0 = *(const float2*)(adjb + ao);
            float2 ad1 = *(const float2*)(adjb + ao + 1024);
            pp[n][0] = pexp2(S[n][0], S[n][1], st.x, st.y, crow0, ad0.x, ad0.y,
                             MAG2, NMAG2, NEG12, C4, C3, C2, C1, ONE2, den0_2);
            pp[n][1] = pexp2(S[n][2], S[n][3], st.x, st.y, crow1, ad1.x, ad1.y,
                             MAG2, NMAG2, NEG12, C4, C3, C2, C1, ONE2, den1_2);
        }

        // O += P @ V
#pragma unroll
        for (int dp = 0; dp < 4; dp++) {
#pragma unroll
            for (int kk = 0; kk < 4; kk++) {
                unsigned vf[4];
                ldm4t(vf, vbase + ((unsigned)(16 * kk + lrowV) << 7) + vcol[dp]);
                unsigned pa[4] = {pp[2 * kk][0], pp[2 * kk][1], pp[2 * kk + 1][0], pp[2 * kk + 1][1]};
                mma16(Ot[2 * dp],     pa, vf[0], vf[1]);
                mma16(Ot[2 * dp + 1], pa, vf[2], vf[3]);
            }
        }
        __syncthreads();

        if (t + 2 < TILES) {
            if (tid == 0) {
                mb_exptx(mbu + 8 * b, 32768);
                int x = kvb + (t + 2) * 64;
                tma2d(tmp, su + ADJ_OFF + b * 32768,         x,      q0, mbu + 8 * b);
                tma2d(tmp, su + ADJ_OFF + b * 32768 + 16384, x + 32, q0, mbu + 8 * b);
            }
            STAGE_KV(t + 2, b);
        }
        cpcommit();
    }

    // unpack packed dens, reduce across quad, write partials
    float d0l, d0h, d1l, d1h;
    asm("mov.b64 {%0, %1}, %2;" : "=f"(d0l), "=f"(d0h) : "l"(den0_2));
    asm("mov.b64 {%0, %1}, %2;" : "=f"(d1l), "=f"(d1h) : "l"(den1_2));
    float den0 = d0l + d0h, den1 = d1l + d1h;
    den0 += __shfl_xor_sync(0xffffffffu, den0, 1);
    den0 += __shfl_xor_sync(0xffffffffu, den0, 2);
    den1 += __shfl_xor_sync(0xffffffffu, den1, 1);
    den1 += __shfl_xor_sync(0xffffffffu, den1, 2);
    if (qd == 0) {
        g_denp[sp][gr] = den0;
        g_denp[sp][gr + 8] = den1;
    }
#pragma unroll
    for (int n = 0; n < 8; n++) {
        float* o0 = &g_aggp[sp][(size_t)gr * 64 + n * 8 + c2];
        *(float2*)o0 = make_float2(Ot[n][0], Ot[n][1]);
        *(float2*)(o0 + 512) = make_float2(Ot[n][2], Ot[n][3]);
    }
}

// ---------------------------------------------------------------------------
// K3: combine 8 partials (float2 lanes); z = h + num/den ; LN ; head MLP.
__global__ __launch_bounds__(256) void k_epi(
    const float* __restrict__ sa, const float* __restrict__ lng, const float* __restrict__ lnb,
    const float* __restrict__ wa1, const float* __restrict__ ba1,
    const float* __restrict__ wa2, const float* __restrict__ ba2,
    float* __restrict__ out) {
    __shared__ float sAi[8][68];
    const int warp = threadIdx.x >> 5;
    const int lane = threadIdx.x & 31;
    const int row = blockIdx.x * 8 + warp;
    const int c = lane << 1;

    float den = 0.f;
    float nx = 0.f, ny = 0.f;
#pragma unroll
    for (int s = 0; s < SPLIT; s++) {
        den += g_denp[s][row];
        float2 t = *(const float2*)&g_aggp[s][row * 64 + c];
        nx += t.x; ny += t.y;
    }
    float invd = 1.0f / den;
    float2 h2 = *(const float2*)&g_h[row * 64 + c];
    float z0 = h2.x + nx * invd;
    float z1 = h2.y + ny * invd;
    float s = z0 + z1;
#pragma unroll
    for (int o = 16; o >= 1; o >>= 1) s += __shfl_xor_sync(0xffffffffu, s, o);
    float mu = s * (1.0f / 64.0f);
    float d0 = z0 - mu, d1 = z1 - mu;
    float v = d0 * d0 + d1 * d1;
#pragma unroll
    for (int o = 16; o >= 1; o >>= 1) v += __shfl_xor_sync(0xffffffffu, v, o);
    float inv = rsqrtf(v * (1.0f / 64.0f) + 1e-5f);
    float2 g2 = *(const float2*)&lng[c];
    float2 b2v = *(const float2*)&lnb[c];
    sAi[warp][c]     = fmaf(d0 * inv, g2.x, b2v.x);
    sAi[warp][c + 1] = fmaf(d1 * inv, g2.y, b2v.y);
    if (lane < 2) sAi[warp][64 + lane] = sa[row * 2 + lane];
    __syncwarp();

    float2 bb = *(const float2*)&ba1[c];
    float acc0 = bb.x, acc1 = bb.y;
#pragma unroll 11
    for (int i = 0; i < 66; i++) {
        float av = sAi[warp][i];
        float2 w = *(const float2*)&wa1[i * 64 + c];
        acc0 = fmaf(av, w.x, acc0);
        acc1 = fmaf(av, w.y, acc1);
    }
    acc0 = fmaxf(acc0, 0.0f);
    acc1 = fmaxf(acc1, 0.0f);
    float q0v = fmaf(acc0, wa2[c * 3 + 0], acc1 * wa2[c * 3 + 3]);
    float q1v = fmaf(acc0, wa2[c * 3 + 1], acc1 * wa2[c * 3 + 4]);
    float q2v = fmaf(acc0, wa2[c * 3 + 2], acc1 * wa2[c * 3 + 5]);
#pragma unroll
    for (int o = 16; o >= 1; o >>= 1) {
        q0v += __shfl_xor_sync(0xffffffffu, q0v, o);
        q1v += __shfl_xor_sync(0xffffffffu, q1v, o);
        q2v += __shfl_xor_sync(0xffffffffu, q2v, o);
    }
    if (lane == 0) {
        out[row * 3 + 0] = q0v + ba2[0];
        out[row * 3 + 1] = q1v + ba2[1];
        out[row * 3 + 2] = q2v + ba2[2];
    }
}

// ---------------------------------------------------------------------------
typedef CUresult (*PFN_tmEnc)(CUtensorMap*, CUtensorMapDataType, cuuint32_t, void*,
                              const cuuint64_t*, const cuuint64_t*, const cuuint32_t*,
                              const cuuint32_t*, CUtensorMapInterleave, CUtensorMapSwizzle,
                              CUtensorMapL2promotion, CUtensorMapFloatOOBfill);

extern "C" void kernel_launch(void* const* d_in, const int* in_sizes, int n_in,
                              void* d_out, int out_size) {
    const float* nf    = (const float*)d_in[0];
    const float* adj   = (const float*)d_in[1];
    const float* tc    = (const float*)d_in[2];
    const float* sa    = (const float*)d_in[3];
    const float* w1    = (const float*)d_in[4];
    const float* b1    = (const float*)d_in[5];
    const float* w2    = (const float*)d_in[6];
    const float* b2    = (const float*)d_in[7];
    const float* wq    = (const float*)d_in[8];
    const float* bq    = (const float*)d_in[9];
    const float* wk    = (const float*)d_in[10];
    const float* bk    = (const float*)d_in[11];
    const float* wg    = (const float*)d_in[12];
    const float* bg    = (const float*)d_in[13];
    const float* sbias = (const float*)d_in[14];
    const float* wm    = (const float*)d_in[15];
    const float* bm    = (const float*)d_in[16];
    const float* lng   = (const float*)d_in[17];
    const float* lnb   = (const float*)d_in[18];
    const float* wa1   = (const float*)d_in[19];
    const float* ba1   = (const float*)d_in[20];
    const float* wa2   = (const float*)d_in[21];
    const float* ba2   = (const float*)d_in[22];
    float* out = (float*)d_out;

    // adj tensormap: fp32 [8192, 8192], box [32, 128], SW128
    CUtensorMap tmap;
    {
        PFN_tmEnc fn = nullptr;
        cudaDriverEntryPointQueryResult st;
        cudaGetDriverEntryPoint("cuTensorMapEncodeTiled", (void**)&fn,
                                cudaEnableDefault, &st);
        cuuint64_t dims[2] = {NN, NN};
        cuuint64_t strides[1] = {NN * 4ull};
        cuuint32_t box[2] = {32, 128};
        cuuint32_t es[2] = {1, 1};
        fn(&tmap, CU_TENSOR_MAP_DATA_TYPE_FLOAT32, 2, (void*)adj, dims, strides, box, es,
           CU_TENSOR_MAP_INTERLEAVE_NONE, CU_TENSOR_MAP_SWIZZLE_128B,
           CU_TENSOR_MAP_L2_PROMOTION_L2_128B, CU_TENSOR_MAP_FLOAT_OOB_FILL_NONE);
    }
    cudaFuncSetAttribute(k_attn, cudaFuncAttributeMaxDynamicSharedMemorySize, SMEM_SZ);

    k_prep<<<256, 256>>>(nf, tc, w1, b1, w2, b2, wq, bq, wk, bk, wm, bm, wg, bg);
    k_attn<<<512, 256, SMEM_SZ>>>(tmap, tc, sbias);
    k_epi<<<1024, 256>>>(sa, lng, lnb, wa1, ba1, wa2, ba2, out);
}

// round 10
// speedup vs baseline: 1.9767x; 1.0330x over previous
#include <cuda_runtime.h>
#include <cuda.h>
#include <cuda_bf16.h>

#define NN 8192
#define L2E 1.4426950408889634f
#define SPLIT 8
#define TILES 16

// smem layout (bytes) for k_attn
#define ADJ_OFF 0            // 2 x 32768
#define K_OFF   65536        // 2 x 8192
#define V_OFF   81920        // 2 x 8192
#define STK_OFF 98304        // 2 x 256
#define MB_OFF  98816        // 2 x 8
#define SMEM_SZ 98944

// k_prep dynamic smem: sA (8KB) + 3 weight buffers (48KB)
#define PREP_SMEM 57344

// Scratch (no allocation allowed)
__device__ float g_h[NN * 64];
__device__ float g_aggp[SPLIT][NN * 64];
__device__ float g_denp[SPLIT][NN];
__device__ __nv_bfloat16 g_qb[NN * 64];
__device__ __nv_bfloat16 g_kb[NN * 64];
__device__ __nv_bfloat16 g_mb[NN * 64];
__device__ float g_stk[NN];

// ---------------------------------------------------------------------------
__device__ __forceinline__ unsigned s2u(const void* p) {
    return (unsigned)__cvta_generic_to_shared(p);
}
__device__ __forceinline__ void cpa16(unsigned d, const void* s) {
    asm volatile("cp.async.cg.shared.global [%0],[%1],16;" :: "r"(d), "l"(s));
}
__device__ __forceinline__ void cpa4(unsigned d, const void* s) {
    asm volatile("cp.async.ca.shared.global [%0],[%1],4;" :: "r"(d), "l"(s));
}
__device__ __forceinline__ void cpcommit() { asm volatile("cp.async.commit_group;"); }
template <int N> __device__ __forceinline__ void cpwait() {
    asm volatile("cp.async.wait_group %0;" :: "n"(N));
}
__device__ __forceinline__ void mb_init(unsigned a, unsigned c) {
    asm volatile("mbarrier.init.shared.b64 [%0], %1;" :: "r"(a), "r"(c));
}
__device__ __forceinline__ void mb_exptx(unsigned a, unsigned b) {
    asm volatile("mbarrier.arrive.expect_tx.shared.b64 _, [%0], %1;" :: "r"(a), "r"(b) : "memory");
}
__device__ __forceinline__ void mb_wait(unsigned a, unsigned ph) {
    asm volatile(
        "{\n\t.reg .pred P;\n\t"
        "W%=:\n\t"
        "mbarrier.try_wait.parity.acquire.cta.shared::cta.b64 P, [%0], %1, 0x989680;\n\t"
        "@!P bra W%=;\n\t}"
        :: "r"(a), "r"(ph) : "memory");
}
__device__ __forceinline__ void tma2d(unsigned long long m, unsigned dst, int x, int y, unsigned mb) {
    asm volatile(
        "cp.async.bulk.tensor.2d.shared::cta.global.tile.mbarrier::complete_tx::bytes "
        "[%0], [%1, {%2, %3}], [%4];"
        :: "r"(dst), "l"(m), "r"(x), "r"(y), "r"(mb) : "memory");
}
__device__ __forceinline__ void ldm4(unsigned r[4], unsigned a) {
    asm volatile("ldmatrix.sync.aligned.m8n8.x4.shared.b16 {%0,%1,%2,%3}, [%4];"
                 : "=r"(r[0]), "=r"(r[1]), "=r"(r[2]), "=r"(r[3]) : "r"(a));
}
__device__ __forceinline__ void ldm4t(unsigned r[4], unsigned a) {
    asm volatile("ldmatrix.sync.aligned.m8n8.x4.trans.shared.b16 {%0,%1,%2,%3}, [%4];"
                 : "=r"(r[0]), "=r"(r[1]), "=r"(r[2]), "=r"(r[3]) : "r"(a));
}
__device__ __forceinline__ void mma16(float d[4], const unsigned a[4], unsigned b0, unsigned b1) {
    asm volatile("mma.sync.aligned.m16n8k16.row.col.f32.bf16.bf16.f32 "
                 "{%0,%1,%2,%3}, {%4,%5,%6,%7}, {%8,%9}, {%0,%1,%2,%3};"
                 : "+f"(d[0]), "+f"(d[1]), "+f"(d[2]), "+f"(d[3])
                 : "r"(a[0]), "r"(a[1]), "r"(a[2]), "r"(a[3]), "r"(b0), "r"(b1));
}
__device__ __forceinline__ unsigned long long pk2(float x) {
    unsigned long long r;
    asm("mov.b64 %0, {%1, %1};" : "=l"(r) : "f"(x));
    return r;
}

// Packed pair: P = adj * 2^(S + crow*st) for two adjacent columns; accumulates
// packed den; returns bf16x2. Non-volatile: pure function of inputs, lets
// ptxas interleave chunks.
__device__ __forceinline__ unsigned pexp2(
    float s0, float s1, float stx, float sty, float crow, float a0, float a1,
    unsigned long long MAG2, unsigned long long NMAG2, unsigned long long NEG12,
    unsigned long long C4, unsigned long long C3, unsigned long long C2,
    unsigned long long C1, unsigned long long ONE2,
    unsigned long long& den2) {
    unsigned out;
    asm(
        "{\n\t"
        ".reg .b64 S2, st2, cr2, ad2, t2, rb2, r2, f2, p2, sc2;\n\t"
        ".reg .b32 il, ih;\n\t"
        ".reg .f32 sl, sh, pl, ph;\n\t"
        "mov.b64 S2, {%2, %3};\n\t"
        "mov.b64 st2, {%4, %5};\n\t"
        "mov.b64 cr2, {%6, %6};\n\t"
        "mov.b64 ad2, {%7, %8};\n\t"
        "fma.rn.f32x2 t2, cr2, st2, S2;\n\t"
        "add.rn.f32x2 rb2, t2, %9;\n\t"
        "add.rn.f32x2 r2, rb2, %10;\n\t"
        "fma.rn.f32x2 f2, r2, %11, t2;\n\t"
        "fma.rn.f32x2 p2, f2, %12, %13;\n\t"
        "fma.rn.f32x2 p2, f2, p2, %14;\n\t"
        "fma.rn.f32x2 p2, f2, p2, %15;\n\t"
        "fma.rn.f32x2 p2, f2, p2, %16;\n\t"
        "mov.b64 {il, ih}, rb2;\n\t"
        "shl.b32 il, il, 23;\n\t"
        "shl.b32 ih, ih, 23;\n\t"
        "add.s32 il, il, 0x3f800000;\n\t"
        "add.s32 ih, ih, 0x3f800000;\n\t"
        "mov.b32 sl, il;\n\t"
        "mov.b32 sh, ih;\n\t"
        "mov.b64 sc2, {sl, sh};\n\t"
        "mul.rn.f32x2 sc2, sc2, ad2;\n\t"
        "mul.rn.f32x2 p2, p2, sc2;\n\t"
        "add.rn.f32x2 %1, %1, p2;\n\t"
        "mov.b64 {pl, ph}, p2;\n\t"
        "cvt.rn.bf16x2.f32 %0, ph, pl;\n\t"
        "}"
        : "=r"(out), "+l"(den2)
        : "f"(s0), "f"(s1), "f"(stx), "f"(sty), "f"(crow), "f"(a0), "f"(a1),
          "l"(MAG2), "l"(NMAG2), "l"(NEG12), "l"(C4), "l"(C3), "l"(C2),
          "l"(C1), "l"(ONE2));
    return out;
}

// ---------------------------------------------------------------------------
__device__ __forceinline__ void store_bf16_row4(__nv_bfloat16* dst, const float* a, float s) {
    __nv_bfloat162 v01, v23;
    v01.x = __float2bfloat16(a[0] * s); v01.y = __float2bfloat16(a[1] * s);
    v23.x = __float2bfloat16(a[2] * s); v23.y = __float2bfloat16(a[3] * s);
    ((__nv_bfloat162*)dst)[0] = v01;
    ((__nv_bfloat162*)dst)[1] = v23;
}

// K1: BM=32, grid 256. Single fused pass for q/k/m; weights via cp.async,
// overlapped with compute.
__global__ __launch_bounds__(256) void k_prep(
    const float* __restrict__ nf, const float* __restrict__ tc,
    const float* __restrict__ w1, const float* __restrict__ b1,
    const float* __restrict__ w2, const float* __restrict__ b2,
    const float* __restrict__ wq, const float* __restrict__ bq,
    const float* __restrict__ wk, const float* __restrict__ bk,
    const float* __restrict__ wm, const float* __restrict__ bm,
    const float* __restrict__ wg, const float* __restrict__ bg) {
    extern __shared__ __align__(16) float dsmf[];
    float* sA  = dsmf;          // 32x64
    float* sW0 = dsmf + 2048;   // w2, then wm
    float* sW1 = dsmf + 6144;   // wq
    float* sW2 = dsmf + 10240;  // wk
    __shared__ float sG[65];

    const int tid = threadIdx.x;
    const int r0 = (tid >> 4) << 1;
    const int c0 = (tid & 15) << 2;
    const int q0 = blockIdx.x * 32;
    const float tc0 = tc[0], tc1 = tc[1];

    // async weight prefetch: group A = w2 ; group B = wq, wk
    {
        unsigned d = s2u(sW0) + tid * 16;
        const char* s = (const char*)w2 + tid * 16;
#pragma unroll
        for (int i = 0; i < 4; i++) cpa16(d + i * 4096, s + i * 4096);
        cpcommit();
        unsigned d1 = s2u(sW1) + tid * 16;
        const char* s1 = (const char*)wq + tid * 16;
        unsigned d2 = s2u(sW2) + tid * 16;
        const char* s2 = (const char*)wk + tid * 16;
#pragma unroll
        for (int i = 0; i < 4; i++) { cpa16(d1 + i * 4096, s1 + i * 4096); cpa16(d2 + i * 4096, s2 + i * 4096); }
        cpcommit();
    }

    if (tid < 32) g_stk[q0 + tid] = nf[(q0 + tid) * 3 + 2];
    if (tid < 64) {
        float v = fmaf(tc0, wg[tid], fmaf(tc1, wg[64 + tid], bg[tid]));
        sG[tid] = 1.0f / (1.0f + __expf(-v));
    }

    // Stage 0: a = relu(x @ w1 + b1) -> sA
    float x0[2], x1[2], x2[2];
#pragma unroll
    for (int i = 0; i < 2; i++) {
        int row = q0 + r0 + i;
        x0[i] = nf[row * 3 + 0]; x1[i] = nf[row * 3 + 1]; x2[i] = nf[row * 3 + 2];
    }
#pragma unroll
    for (int c = 0; c < 4; c++) {
        int col = c0 + c;
        float wv0 = w1[col], wv1 = w1[64 + col], wv2 = w1[128 + col];
        float bb = fmaf(tc0, w1[192 + col], fmaf(tc1, w1[256 + col], b1[col]));
#pragma unroll
        for (int i = 0; i < 2; i++) {
            float a = fmaf(x0[i], wv0, fmaf(x1[i], wv1, fmaf(x2[i], wv2, bb)));
            sA[(r0 + i) * 64 + col] = fmaxf(a, 0.0f);
        }
    }
    cpwait<1>();          // w2 landed
    __syncthreads();
    if (tid == 0) {
        float s = 0.0f;
#pragma unroll 8
        for (int i = 0; i < 64; i++) s += sG[i];
        sG[64] = s * (1.0f / 64.0f) * 0.125f * L2E;   // gate/8 * log2e
    }

    // Stage 1: h = a @ w2 + b2
    float acc[2][4];
    {
        float4 bb = *(const float4*)&b2[c0];
#pragma unroll
        for (int i = 0; i < 2; i++) { acc[i][0] = bb.x; acc[i][1] = bb.y; acc[i][2] = bb.z; acc[i][3] = bb.w; }
#pragma unroll 8
        for (int j = 0; j < 64; j++) {
            float4 wv = *(const float4*)&sW0[j * 64 + c0];
#pragma unroll
            for (int i = 0; i < 2; i++) {
                float av = sA[(r0 + i) * 64 + j];
                acc[i][0] = fmaf(av, wv.x, acc[i][0]);
                acc[i][1] = fmaf(av, wv.y, acc[i][1]);
                acc[i][2] = fmaf(av, wv.z, acc[i][2]);
                acc[i][3] = fmaf(av, wv.w, acc[i][3]);
            }
        }
    }
    __syncthreads();      // all reads of sA / sW0 done

    // overwrite sA with h; prefetch wm into sW0
    {
        unsigned d = s2u(sW0) + tid * 16;
        const char* s = (const char*)wm + tid * 16;
#pragma unroll
        for (int i = 0; i < 4; i++) cpa16(d + i * 4096, s + i * 4096);
        cpcommit();
    }
#pragma unroll
    for (int i = 0; i < 2; i++) {
        float4 hv = make_float4(acc[i][0], acc[i][1], acc[i][2], acc[i][3]);
        *(float4*)&sA[(r0 + i) * 64 + c0] = hv;
        *(float4*)&g_h[(q0 + r0 + i) * 64 + c0] = hv;
    }
    cpwait<0>();          // wq, wk, wm all landed
    __syncthreads();

    // Stage 2: fused q/k/m GEMM — one pass over sA
    float aq[2][4], ak[2][4], am[2][4];
    {
        float4 bbq = *(const float4*)&bq[c0];
        float4 bbk = *(const float4*)&bk[c0];
        float4 bbm = *(const float4*)&bm[c0];
#pragma unroll
        for (int i = 0; i < 2; i++) {
            aq[i][0] = bbq.x; aq[i][1] = bbq.y; aq[i][2] = bbq.z; aq[i][3] = bbq.w;
            ak[i][0] = bbk.x; ak[i][1] = bbk.y; ak[i][2] = bbk.z; ak[i][3] = bbk.w;
            am[i][0] = bbm.x; am[i][1] = bbm.y; am[i][2] = bbm.z; am[i][3] = bbm.w;
        }
    }
#pragma unroll 4
    for (int j = 0; j < 64; j++) {
        float4 wvq = *(const float4*)&sW1[j * 64 + c0];
        float4 wvk = *(const float4*)&sW2[j * 64 + c0];
        float4 wvm = *(const float4*)&sW0[j * 64 + c0];
#pragma unroll
        for (int i = 0; i < 2; i++) {
            float av = sA[(r0 + i) * 64 + j];
            aq[i][0] = fmaf(av, wvq.x, aq[i][0]);
            aq[i][1] = fmaf(av, wvq.y, aq[i][1]);
            aq[i][2] = fmaf(av, wvq.z, aq[i][2]);
            aq[i][3] = fmaf(av, wvq.w, aq[i][3]);
            ak[i][0] = fmaf(av, wvk.x, ak[i][0]);
            ak[i][1] = fmaf(av, wvk.y, ak[i][1]);
            ak[i][2] = fmaf(av, wvk.z, ak[i][2]);
            ak[i][3] = fmaf(av, wvk.w, ak[i][3]);
            am[i][0] = fmaf(av, wvm.x, am[i][0]);
            am[i][1] = fmaf(av, wvm.y, am[i][1]);
            am[i][2] = fmaf(av, wvm.z, am[i][2]);
            am[i][3] = fmaf(av, wvm.w, am[i][3]);
        }
    }
    {
        float qs = sG[64];
#pragma unroll
        for (int i = 0; i < 2; i++) {
            store_bf16_row4(&g_qb[(q0 + r0 + i) * 64 + c0], aq[i], qs);
            store_bf16_row4(&g_kb[(q0 + r0 + i) * 64 + c0], ak[i], 1.0f);
            store_bf16_row4(&g_mb[(q0 + r0 + i) * 64 + c0], am[i], 1.0f);
        }
    }
}

// ---------------------------------------------------------------------------
// K2: flash attention. BM=128, BN=64, split-KV x8. adj via TMA, packed-f32x2
// pointwise INTERLEAVED with P@V per k-chunk, register-resident P.
__global__ __launch_bounds__(256) void k_attn(const __grid_constant__ CUtensorMap tmap,
                                              const float* __restrict__ tc,
                                              const float* __restrict__ sb) {
    extern __shared__ __align__(128) char dsm[];
    const unsigned su = s2u(dsm);
    const int tid = threadIdx.x;
    const int lane = tid & 31;
    const int wr = tid >> 5;
    const int r = lane >> 2;
    const int qd = lane & 3;
    const int c2 = qd << 1;
    const int qi = blockIdx.x >> 3;
    const int sp = blockIdx.x & 7;
    const int q0 = qi * 128;
    const int kvb = sp * 1024;
    const int gr = q0 + wr * 16 + r;
    const unsigned mbu = su + MB_OFF;

    if (tid == 0) { mb_init(mbu, 1); mb_init(mbu + 8, 1); }
    __syncthreads();

    const unsigned long long tmp = (unsigned long long)&tmap;
    if (tid == 0) {
        mb_exptx(mbu, 32768);
        tma2d(tmp, su + ADJ_OFF,         kvb,      q0, mbu);
        tma2d(tmp, su + ADJ_OFF + 16384, kvb + 32, q0, mbu);
        mb_exptx(mbu + 8, 32768);
        tma2d(tmp, su + ADJ_OFF + 32768, kvb + 64, q0, mbu + 8);
        tma2d(tmp, su + ADJ_OFF + 49152, kvb + 96, q0, mbu + 8);
    }

    // K/V staging (SW128 swizzled dense 64x64 bf16)
    const int srow = tid >> 3, sc = tid & 7;
    const unsigned sdof = (unsigned)(((srow << 7) + (sc << 4)) ^ (16 * (srow & 7)));
#define STAGE_KV(T, B)                                                              \
    {                                                                               \
        const __nv_bfloat16* kg = g_kb + (size_t)(kvb + (T) * 64) * 64;             \
        const __nv_bfloat16* vg = g_mb + (size_t)(kvb + (T) * 64) * 64;             \
        unsigned kd = su + K_OFF + (B) * 8192 + sdof;                               \
        unsigned vd = su + V_OFF + (B) * 8192 + sdof;                               \
        cpa16(kd, kg + srow * 64 + sc * 8);                                         \
        cpa16(kd + 4096, kg + (srow + 32) * 64 + sc * 8);                           \
        cpa16(vd, vg + srow * 64 + sc * 8);                                         \
        cpa16(vd + 4096, vg + (srow + 32) * 64 + sc * 8);                           \
        if (tid < 64) cpa4(su + STK_OFF + (B) * 256 + tid * 4, g_stk + kvb + (T) * 64 + tid); \
    }
    STAGE_KV(0, 0); cpcommit();
    STAGE_KV(1, 1); cpcommit();

    // Q fragments in registers
    unsigned qf[4][4];
#pragma unroll
    for (int kk = 0; kk < 4; kk++) {
        const __nv_bfloat16* qp = g_qb + (size_t)gr * 64 + kk * 16 + c2;
        qf[kk][0] = *(const unsigned*)qp;
        qf[kk][1] = *(const unsigned*)(qp + 512);
        qf[kk][2] = *(const unsigned*)(qp + 8);
        qf[kk][3] = *(const unsigned*)(qp + 520);
    }
    const float sbl = sb[0] * (1.0f - tc[0]) * L2E;
    const float crow0 = sbl * g_stk[gr];
    const float crow1 = sbl * g_stk[gr + 8];

    // packed constants (warp-uniform -> UR promotion)
    const unsigned long long MAG2 = pk2(12582912.0f);
    const unsigned long long NMAG2 = pk2(-12582912.0f);
    const unsigned long long NEG12 = pk2(-1.0f);
    const unsigned long long C4 = pk2(0.0096181291f);
    const unsigned long long C3 = pk2(0.0555041087f);
    const unsigned long long C2 = pk2(0.2402265070f);
    const unsigned long long C1 = pk2(0.6931471806f);
    const unsigned long long ONE2 = pk2(1.0f);

    // lane-constant smem addressing
    const unsigned swz = 16u * (lane & 7);
    const unsigned lrowK = (((lane >> 4) & 1) << 3) + (lane & 7);
    const unsigned lrowV = (((lane >> 3) & 1) << 3) + (lane & 7);
    const unsigned kc16 = ((lane >> 3) & 1) << 4;
    const unsigned vc16 = ((lane >> 4) & 1) << 4;
    unsigned kcol[4], vcol[4];
#pragma unroll
    for (int i = 0; i < 4; i++) {
        kcol[i] = ((unsigned)(i << 5) + kc16) ^ swz;
        vcol[i] = ((unsigned)(i << 5) + vc16) ^ swz;
    }
    const unsigned arow128 = (unsigned)(wr * 16 + r) << 7;
    const unsigned acb = 8u * qd;
    const unsigned aswz = 16u * r;

    float Ot[8][4];
#pragma unroll
    for (int n = 0; n < 8; n++) { Ot[n][0] = Ot[n][1] = Ot[n][2] = Ot[n][3] = 0.f; }
    unsigned long long den0_2 = 0ull, den1_2 = 0ull;

    for (int t = 0; t < TILES; t++) {
        const int b = t & 1;
        mb_wait(mbu + 8 * b, (t >> 1) & 1);
        cpwait<1>();
        __syncthreads();

        const unsigned kbase = su + K_OFF + b * 8192;
        const unsigned vbase = su + V_OFF + b * 8192;
        const char* adjb = dsm + b * 32768;
        const float* stkb = (const float*)(dsm + STK_OFF + b * 256);

        // S = Q @ K^T
        float S[8][4];
#pragma unroll
        for (int n = 0; n < 8; n++) { S[n][0] = S[n][1] = S[n][2] = S[n][3] = 0.f; }
#pragma unroll
        for (int jp = 0; jp < 4; jp++) {
            const unsigned rb = (unsigned)(16 * jp + lrowK) << 7;
#pragma unroll
            for (int kk = 0; kk < 4; kk++) {
                unsigned kf[4];
                ldm4(kf, kbase + rb + kcol[kk]);
                mma16(S[2 * jp],     qf[kk], kf[0], kf[1]);
                mma16(S[2 * jp + 1], qf[kk], kf[2], kf[3]);
            }
        }

        // interleaved pointwise + P@V, per k-chunk of 16 kv
#pragma unroll
        for (int kk = 0; kk < 4; kk++) {
            unsigned pa[4];
#pragma unroll
            for (int u = 0; u < 2; u++) {
                const int n = 2 * kk + u;
                float2 st = *(const float2*)(stkb + n * 8 + c2);
                unsigned ao = ((unsigned)(n >> 2) << 14) + arow128 +
                              ((acb + ((unsigned)(n & 3) << 5)) ^ aswz);
                float2 ad0 = *(const float2*)(adjb + ao);
                float2 ad1 = *(const float2*)(adjb + ao + 1024);
                pa[2 * u]     = pexp2(S[n][0], S[n][1], st.x, st.y, crow0, ad0.x, ad0.y,
                                      MAG2, NMAG2, NEG12, C4, C3, C2, C1, ONE2, den0_2);
                pa[2 * u + 1] = pexp2(S[n][2], S[n][3], st.x, st.y, crow1, ad1.x, ad1.y,
                                      MAG2, NMAG2, NEG12, C4, C3, C2, C1, ONE2, den1_2);
            }
#pragma unroll
            for (int dp = 0; dp < 4; dp++) {
                unsigned vf[4];
                ldm4t(vf, vbase + ((unsigned)(16 * kk + lrowV) << 7) + vcol[dp]);
                mma16(Ot[2 * dp],     pa, vf[0], vf[1]);
                mma16(Ot[2 * dp + 1], pa, vf[2], vf[3]);
            }
        }
        __syncthreads();

        if (t + 2 < TILES) {
            if (tid == 0) {
                mb_exptx(mbu + 8 * b, 32768);
                int x = kvb + (t + 2) * 64;
                tma2d(tmp, su + ADJ_OFF + b * 32768,         x,      q0, mbu + 8 * b);
                tma2d(tmp, su + ADJ_OFF + b * 32768 + 16384, x + 32, q0, mbu + 8 * b);
            }
            STAGE_KV(t + 2, b);
        }
        cpcommit();
    }

    // unpack packed dens, reduce across quad, write partials
    float d0l, d0h, d1l, d1h;
    asm("mov.b64 {%0, %1}, %2;" : "=f"(d0l), "=f"(d0h) : "l"(den0_2));
    asm("mov.b64 {%0, %1}, %2;" : "=f"(d1l), "=f"(d1h) : "l"(den1_2));
    float den0 = d0l + d0h, den1 = d1l + d1h;
    den0 += __shfl_xor_sync(0xffffffffu, den0, 1);
    den0 += __shfl_xor_sync(0xffffffffu, den0, 2);
    den1 += __shfl_xor_sync(0xffffffffu, den1, 1);
    den1 += __shfl_xor_sync(0xffffffffu, den1, 2);
    if (qd == 0) {
        g_denp[sp][gr] = den0;
        g_denp[sp][gr + 8] = den1;
    }
#pragma unroll
    for (int n = 0; n < 8; n++) {
        float* o0 = &g_aggp[sp][(size_t)gr * 64 + n * 8 + c2];
        *(float2*)o0 = make_float2(Ot[n][0], Ot[n][1]);
        *(float2*)(o0 + 512) = make_float2(Ot[n][2], Ot[n][3]);
    }
}

// ---------------------------------------------------------------------------
// K3: combine 8 partials (float2 lanes); z = h + num/den ; LN ; head MLP.
__global__ __launch_bounds__(256) void k_epi(
    const float* __restrict__ sa, const float* __restrict__ lng, const float* __restrict__ lnb,
    const float* __restrict__ wa1, const float* __restrict__ ba1,
    const float* __restrict__ wa2, const float* __restrict__ ba2,
    float* __restrict__ out) {
    __shared__ float sAi[8][68];
    const int warp = threadIdx.x >> 5;
    const int lane = threadIdx.x & 31;
    const int row = blockIdx.x * 8 + warp;
    const int c = lane << 1;

    float den = 0.f;
    float nx = 0.f, ny = 0.f;
#pragma unroll
    for (int s = 0; s < SPLIT; s++) {
        den += g_denp[s][row];
        float2 t = *(const float2*)&g_aggp[s][row * 64 + c];
        nx += t.x; ny += t.y;
    }
    float invd = 1.0f / den;
    float2 h2 = *(const float2*)&g_h[row * 64 + c];
    float z0 = h2.x + nx * invd;
    float z1 = h2.y + ny * invd;
    float s = z0 + z1;
#pragma unroll
    for (int o = 16; o >= 1; o >>= 1) s += __shfl_xor_sync(0xffffffffu, s, o);
    float mu = s * (1.0f / 64.0f);
    float d0 = z0 - mu, d1 = z1 - mu;
    float v = d0 * d0 + d1 * d1;
#pragma unroll
    for (int o = 16; o >= 1; o >>= 1) v += __shfl_xor_sync(0xffffffffu, v, o);
    float inv = rsqrtf(v * (1.0f / 64.0f) + 1e-5f);
    float2 g2 = *(const float2*)&lng[c];
    float2 b2v = *(const float2*)&lnb[c];
    sAi[warp][c]     = fmaf(d0 * inv, g2.x, b2v.x);
    sAi[warp][c + 1] = fmaf(d1 * inv, g2.y, b2v.y);
    if (lane < 2) sAi[warp][64 + lane] = sa[row * 2 + lane];
    __syncwarp();

    float2 bb = *(const float2*)&ba1[c];
    float acc0 = bb.x, acc1 = bb.y;
#pragma unroll 11
    for (int i = 0; i < 66; i++) {
        float av = sAi[warp][i];
        float2 w = *(const float2*)&wa1[i * 64 + c];
        acc0 = fmaf(av, w.x, acc0);
        acc1 = fmaf(av, w.y, acc1);
    }
    acc0 = fmaxf(acc0, 0.0f);
    acc1 = fmaxf(acc1, 0.0f);
    float q0v = fmaf(acc0, wa2[c * 3 + 0], acc1 * wa2[c * 3 + 3]);
    float q1v = fmaf(acc0, wa2[c * 3 + 1], acc1 * wa2[c * 3 + 4]);
    float q2v = fmaf(acc0, wa2[c * 3 + 2], acc1 * wa2[c * 3 + 5]);
#pragma unroll
    for (int o = 16; o >= 1; o >>= 1) {
        q0v += __shfl_xor_sync(0xffffffffu, q0v, o);
        q1v += __shfl_xor_sync(0xffffffffu, q1v, o);
        q2v += __shfl_xor_sync(0xffffffffu, q2v, o);
    }
    if (lane == 0) {
        out[row * 3 + 0] = q0v + ba2[0];
        out[row * 3 + 1] = q1v + ba2[1];
        out[row * 3 + 2] = q2v + ba2[2];
    }
}

// ---------------------------------------------------------------------------
typedef CUresult (*PFN_tmEnc)(CUtensorMap*, CUtensorMapDataType, cuuint32_t, void*,
                              const cuuint64_t*, const cuuint64_t*, const cuuint32_t*,
                              const cuuint32_t*, CUtensorMapInterleave, CUtensorMapSwizzle,
                              CUtensorMapL2promotion, CUtensorMapFloatOOBfill);

extern "C" void kernel_launch(void* const* d_in, const int* in_sizes, int n_in,
                              void* d_out, int out_size) {
    const float* nf    = (const float*)d_in[0];
    const float* adj   = (const float*)d_in[1];
    const float* tc    = (const float*)d_in[2];
    const float* sa    = (const float*)d_in[3];
    const float* w1    = (const float*)d_in[4];
    const float* b1    = (const float*)d_in[5];
    const float* w2    = (const float*)d_in[6];
    const float* b2    = (const float*)d_in[7];
    const float* wq    = (const float*)d_in[8];
    const float* bq    = (const float*)d_in[9];
    const float* wk    = (const float*)d_in[10];
    const float* bk    = (const float*)d_in[11];
    const float* wg    = (const float*)d_in[12];
    const float* bg    = (const float*)d_in[13];
    const float* sbias = (const float*)d_in[14];
    const float* wm    = (const float*)d_in[15];
    const float* bm    = (const float*)d_in[16];
    const float* lng   = (const float*)d_in[17];
    const float* lnb   = (const float*)d_in[18];
    const float* wa1   = (const float*)d_in[19];
    const float* ba1   = (const float*)d_in[20];
    const float* wa2   = (const float*)d_in[21];
    const float* ba2   = (const float*)d_in[22];
    float* out = (float*)d_out;

    // adj tensormap: fp32 [8192, 8192], box [32, 128], SW128
    CUtensorMap tmap;
    {
        PFN_tmEnc fn = nullptr;
        cudaDriverEntryPointQueryResult st;
        cudaGetDriverEntryPoint("cuTensorMapEncodeTiled", (void**)&fn,
                                cudaEnableDefault, &st);
        cuuint64_t dims[2] = {NN, NN};
        cuuint64_t strides[1] = {NN * 4ull};
        cuuint32_t box[2] = {32, 128};
        cuuint32_t es[2] = {1, 1};
        fn(&tmap, CU_TENSOR_MAP_DATA_TYPE_FLOAT32, 2, (void*)adj, dims, strides, box, es,
           CU_TENSOR_MAP_INTERLEAVE_NONE, CU_TENSOR_MAP_SWIZZLE_128B,
           CU_TENSOR_MAP_L2_PROMOTION_L2_128B, CU_TENSOR_MAP_FLOAT_OOB_FILL_NONE);
    }
    cudaFuncSetAttribute(k_attn, cudaFuncAttributeMaxDynamicSharedMemorySize, SMEM_SZ);
    cudaFuncSetAttribute(k_prep, cudaFuncAttributeMaxDynamicSharedMemorySize, PREP_SMEM);

    k_prep<<<256, 256, PREP_SMEM>>>(nf, tc, w1, b1, w2, b2, wq, bq, wk, bk, wm, bm, wg, bg);
    k_attn<<<512, 256, SMEM_SZ>>>(tmap, tc, sbias);
    k_epi<<<1024, 256>>>(sa, lng, lnb, wa1, ba1, wa2, ba2, out);
}